// round 6
// baseline (speedup 1.0000x reference)
#include <cuda_runtime.h>
#include <cstdint>

#define BATCH 4
#define S_LEN 2048
#define EMB   1024
#define NH    16
#define DH    64

// Scratch (allocation-free rule: __device__ globals)
__device__ float g_Xs[16777216];   // X pre-split (hi,lo interleaved) [8192,2048]
__device__ float g_Ws[8388608];    // Wq,Wk,Wv,Wo pre-split, 2M floats each
__device__ float g_Q [8388608];    // raw fp32 [B,H,S,Dh]
__device__ float g_Ks[16777216];   // K pre-split [B,H,S,2*Dh]
__device__ float g_V [8388608];    // V tf32-rounded [B,H,S,Dh]
__device__ float g_Ys[16777216];   // attention out pre-split [B,S,2*E]

// ===========================================================================
// Helpers
// ===========================================================================
__device__ __forceinline__ uint32_t smem_u32(const void* p) {
    uint32_t a;
    asm("{ .reg .u64 t; cvta.to.shared.u64 t, %1; cvt.u32.u64 %0, t; }"
        : "=r"(a) : "l"(p));
    return a;
}
__device__ __forceinline__ void cp_async16(uint32_t s, const void* g) {
    asm volatile("cp.async.cg.shared.global [%0], [%1], 16;" :: "r"(s), "l"(g));
}
__device__ __forceinline__ void cp_commit() {
    asm volatile("cp.async.commit_group;" ::: "memory");
}
template <int N>
__device__ __forceinline__ void cp_wait_group() {
    asm volatile("cp.async.wait_group %0;" :: "n"(N) : "memory");
}
__device__ __forceinline__ void mma_tf32(float* c, const uint32_t* a, const uint32_t* b) {
    asm volatile(
        "mma.sync.aligned.m16n8k8.row.col.f32.tf32.tf32.f32 "
        "{%0,%1,%2,%3}, {%4,%5,%6,%7}, {%8,%9}, {%0,%1,%2,%3};"
        : "+f"(c[0]), "+f"(c[1]), "+f"(c[2]), "+f"(c[3])
        : "r"(a[0]), "r"(a[1]), "r"(a[2]), "r"(a[3]), "r"(b[0]), "r"(b[1]));
}
__device__ __forceinline__ uint32_t f2tf32(float x) {
    uint32_t r;
    asm("cvt.rna.tf32.f32 %0, %1;" : "=r"(r) : "f"(x));
    return r;
}
__device__ __forceinline__ float rtf(float x) {   // round to tf32
    return __uint_as_float(f2tf32(x));
}

// ===========================================================================
// Pre-split: x -> interleaved (tf32 hi, tf32 lo) pairs.
// ===========================================================================
__global__ __launch_bounds__(256) void split_tf32(const float4* __restrict__ src,
                                                  float4* __restrict__ dst, int n4)
{
    const int i = blockIdx.x * 256 + threadIdx.x;
    if (i >= n4) return;
    const float4 v = src[i];
    const float hx = rtf(v.x), hy = rtf(v.y), hz = rtf(v.z), hw = rtf(v.w);
    dst[2 * i]     = make_float4(hx, rtf(v.x - hx), hy, rtf(v.y - hy));
    dst[2 * i + 1] = make_float4(hz, rtf(v.z - hz), hw, rtf(v.w - hw));
}

// ===========================================================================
// Pre-split 3xTF32 GEMM: C[M,N] = A[M,K] * W[N,K]^T. Operands arrive as
// interleaved (hi,lo) pairs — inner loop is pure LDS.64 + HMMA, zero ALU.
// BM=128, BN=128, BK=32 (=64 interleaved floats); 8 warps (4Mx2N).
// ===========================================================================
#define PSPIT   72                      // floats per SMEM row (64 data + 8 pad)
#define PSSTAGE (2 * 128 * PSPIT)       // floats per stage (A + B tiles)
#define PSGSMEM (2 * PSSTAGE * 4)       // 147456 bytes

template <bool SCATTER>
__global__ __launch_bounds__(256) void gemm_ps(float* __restrict__ outp)
{
    const float* Ag;
    const float* Bg;
    if (SCATTER) {
        Ag = g_Xs;
        Bg = g_Ws + (size_t)blockIdx.z * 2097152;
    } else {
        Ag = g_Ys;
        Bg = g_Ws + 6291456;
    }

    extern __shared__ __align__(16) float sm[];
    const int tid  = threadIdx.x;
    const int wid  = tid >> 5;
    const int lane = tid & 31;
    const int m0   = blockIdx.x * 128;
    const int n0   = blockIdx.y * 128;
    const int wm   = (wid >> 1) * 32;
    const int wn   = (wid & 1) * 64;
    const int q    = lane & 3;
    const int g8   = lane >> 2;

    const int ldrow = tid >> 4;          // 0..15 (+16*j)
    const int ldc4  = tid & 15;

    const uint32_t sbase = smem_u32(sm);
    const float* Arow = Ag + (size_t)m0 * 2048;
    const float* Brow = Bg + (size_t)n0 * 2048;

    // preload chunk 0
#pragma unroll
    for (int j = 0; j < 8; j++) {
        const int row = ldrow + 16 * j;
        cp_async16(sbase + (uint32_t)((row * PSPIT + ldc4 * 4) * 4),
                   Arow + (size_t)row * 2048 + ldc4 * 4);
        cp_async16(sbase + (uint32_t)((128 * PSPIT + row * PSPIT + ldc4 * 4) * 4),
                   Brow + (size_t)row * 2048 + ldc4 * 4);
    }
    cp_commit();

    float acc[2][8][4];
#pragma unroll
    for (int t = 0; t < 2; t++)
#pragma unroll
        for (int u = 0; u < 8; u++)
#pragma unroll
            for (int r = 0; r < 4; r++) acc[t][u][r] = 0.f;

    for (int kt = 0; kt < 32; kt++) {
        if (kt + 1 < 32) {
            const uint32_t st = ((kt + 1) & 1) * (uint32_t)(PSSTAGE * 4);
            const float* ap = Arow + (size_t)(kt + 1) * 64;
            const float* bp = Brow + (size_t)(kt + 1) * 64;
#pragma unroll
            for (int j = 0; j < 8; j++) {
                const int row = ldrow + 16 * j;
                cp_async16(sbase + st + (uint32_t)((row * PSPIT + ldc4 * 4) * 4),
                           ap + (size_t)row * 2048 + ldc4 * 4);
                cp_async16(sbase + st + (uint32_t)((128 * PSPIT + row * PSPIT + ldc4 * 4) * 4),
                           bp + (size_t)row * 2048 + ldc4 * 4);
            }
            cp_commit();
            cp_wait_group<1>();
        } else {
            cp_wait_group<0>();
        }
        __syncthreads();

        const float* As = sm + (kt & 1) * PSSTAGE;
        const float* Bs = As + 128 * PSPIT;

#pragma unroll
        for (int ks = 0; ks < 4; ks++) {
            const int kq2 = 2 * (ks * 8 + q);
            uint32_t ah[2][4], al[2][4];
#pragma unroll
            for (int t = 0; t < 2; t++) {
                const int r0 = wm + t * 16 + g8;
                const float2 a0 = *(const float2*)&As[r0 * PSPIT + kq2];
                const float2 a1 = *(const float2*)&As[(r0 + 8) * PSPIT + kq2];
                const float2 a2 = *(const float2*)&As[r0 * PSPIT + kq2 + 8];
                const float2 a3 = *(const float2*)&As[(r0 + 8) * PSPIT + kq2 + 8];
                ah[t][0] = __float_as_uint(a0.x); al[t][0] = __float_as_uint(a0.y);
                ah[t][1] = __float_as_uint(a1.x); al[t][1] = __float_as_uint(a1.y);
                ah[t][2] = __float_as_uint(a2.x); al[t][2] = __float_as_uint(a2.y);
                ah[t][3] = __float_as_uint(a3.x); al[t][3] = __float_as_uint(a3.y);
            }
#pragma unroll
            for (int u = 0; u < 8; u++) {
                const int n = wn + u * 8 + g8;
                const float2 b0 = *(const float2*)&Bs[n * PSPIT + kq2];
                const float2 b1 = *(const float2*)&Bs[n * PSPIT + kq2 + 8];
                uint32_t bh[2], bl[2];
                bh[0] = __float_as_uint(b0.x); bl[0] = __float_as_uint(b0.y);
                bh[1] = __float_as_uint(b1.x); bl[1] = __float_as_uint(b1.y);
#pragma unroll
                for (int t = 0; t < 2; t++) {
                    mma_tf32(acc[t][u], ah[t], bh);
                    mma_tf32(acc[t][u], ah[t], bl);
                    mma_tf32(acc[t][u], al[t], bh);
                }
            }
        }
        __syncthreads();
    }

    // ---- epilogue ----
    const int z = SCATTER ? blockIdx.z : 3;
#pragma unroll
    for (int t = 0; t < 2; t++) {
#pragma unroll
        for (int u = 0; u < 8; u++) {
            const int m = m0 + wm + t * 16 + g8;
            const int n = n0 + wn + u * 8 + q * 2;
#pragma unroll
            for (int hh = 0; hh < 2; hh++) {
                const int mm = m + hh * 8;
                const float v0 = acc[t][u][hh * 2];
                const float v1 = acc[t][u][hh * 2 + 1];
                if (SCATTER) {
                    const int bb = mm >> 11, s = mm & 2047;
                    const int h = n >> 6, d0 = n & 63;
                    const size_t e = (((size_t)bb * NH + h) * S_LEN + s) * DH + d0;
                    if (z == 0) {
                        *(float2*)(g_Q + e) = make_float2(v0, v1);
                    } else if (z == 1) {
                        const float h0 = rtf(v0), h1 = rtf(v1);
                        *(float4*)(g_Ks + 2 * e) =
                            make_float4(h0, rtf(v0 - h0), h1, rtf(v1 - h1));
                    } else {
                        *(float2*)(g_V + e) = make_float2(rtf(v0), rtf(v1));
                    }
                } else {
                    *(float2*)(outp + (size_t)mm * EMB + n) = make_float2(v0, v1);
                }
            }
        }
    }
}

// ===========================================================================
// mma.sync flash attention, causal. Block = 128 q-rows; k-tiles of 64.
// K arrives pre-split (hi,lo); V arrives tf32-rounded. Inner loops ALU-free.
// ===========================================================================
#define QPIT 68
#define KPIT 136                             // interleaved K row
#define VPIT 72
#define QP_F   (128 * QPIT)                  // 8704 floats (Q then P)
#define KST_F  (64 * KPIT)                   // 8704 per stage
#define VST_F  (64 * VPIT)                   // 4608 per stage
#define FLASH_SMEM ((QP_F + 2 * KST_F + 2 * VST_F) * 4)   // 141312 B

__global__ __launch_bounds__(256) void flash_mma()
{
    const int qi = blockIdx.x;
    const int bh = blockIdx.y;

    extern __shared__ __align__(16) float sm[];
    float* QP = sm;
    float* Kb = sm + QP_F;
    float* Vb = Kb + 2 * KST_F;

    const int tid  = threadIdx.x;
    const int wid  = tid >> 5;
    const int lane = tid & 31;
    const int g8   = lane >> 2;
    const int q    = lane & 3;
    const int wm   = wid * 16;

    const float* Qg = g_Q  + ((size_t)bh * S_LEN + (size_t)qi * 128) * DH;
    const float* Kg = g_Ks + (size_t)bh * S_LEN * 2 * DH;
    const float* Vg = g_V  + (size_t)bh * S_LEN * DH;

    const uint32_t sbase = smem_u32(sm);
    const uint32_t kboff = (uint32_t)(QP_F * 4);
    const uint32_t vboff = (uint32_t)((QP_F + 2 * KST_F) * 4);

    // ---- Q tile (group 0) ----
#pragma unroll
    for (int j = 0; j < 8; j++) {
        const int f = tid + 256 * j, row = f >> 4, c4 = f & 15;
        cp_async16(sbase + (uint32_t)((row * QPIT + c4 * 4) * 4),
                   Qg + row * DH + c4 * 4);
    }
    cp_commit();
    // ---- K/V tile 0 (group 1): K = 8 f4/thread, V = 4 f4/thread ----
#pragma unroll
    for (int j = 0; j < 8; j++) {
        const int f = tid + 256 * j, row = f >> 5, c4 = f & 31;
        cp_async16(sbase + kboff + (uint32_t)((row * KPIT + c4 * 4) * 4),
                   Kg + row * 2 * DH + c4 * 4);
    }
#pragma unroll
    for (int j = 0; j < 4; j++) {
        const int f = tid + 256 * j, row = f >> 4, c4 = f & 15;
        cp_async16(sbase + vboff + (uint32_t)((row * VPIT + c4 * 4) * 4),
                   Vg + row * DH + c4 * 4);
    }
    cp_commit();

    cp_wait_group<1>();
    __syncthreads();

    // ---- hoist Q fragments (3x split, once); QP becomes the P buffer ----
    uint32_t qh[8][4], ql[8][4];
#pragma unroll
    for (int kc = 0; kc < 8; kc++) {
        const float f0 = QP[(wm + g8) * QPIT + kc * 8 + q];
        const float f1 = QP[(wm + g8 + 8) * QPIT + kc * 8 + q];
        const float f2 = QP[(wm + g8) * QPIT + kc * 8 + q + 4];
        const float f3 = QP[(wm + g8 + 8) * QPIT + kc * 8 + q + 4];
        qh[kc][0] = f2tf32(f0); ql[kc][0] = f2tf32(f0 - __uint_as_float(qh[kc][0]));
        qh[kc][1] = f2tf32(f1); ql[kc][1] = f2tf32(f1 - __uint_as_float(qh[kc][1]));
        qh[kc][2] = f2tf32(f2); ql[kc][2] = f2tf32(f2 - __uint_as_float(qh[kc][2]));
        qh[kc][3] = f2tf32(f3); ql[kc][3] = f2tf32(f3 - __uint_as_float(qh[kc][3]));
    }
    __syncthreads();

    float m0 = -1e30f, m1 = -1e30f, l0 = 0.f, l1 = 0.f;
    float o[8][4];
#pragma unroll
    for (int u = 0; u < 8; u++)
#pragma unroll
        for (int r = 0; r < 4; r++) o[u][r] = 0.f;

    const int row0 = qi * 128 + wm + g8;
    const int row1 = row0 + 8;
    const int last = 2 * qi + 1;

    for (int kt = 0; kt <= last; kt++) {
        if (kt < last) {
            const int st = (kt + 1) & 1;
            const float* kp = Kg + (size_t)(kt + 1) * 64 * 2 * DH;
            const float* vp = Vg + (size_t)(kt + 1) * 64 * DH;
#pragma unroll
            for (int j = 0; j < 8; j++) {
                const int f = tid + 256 * j, row = f >> 5, c4 = f & 31;
                cp_async16(sbase + kboff + (uint32_t)((st * KST_F + row * KPIT + c4 * 4) * 4),
                           kp + row * 2 * DH + c4 * 4);
            }
#pragma unroll
            for (int j = 0; j < 4; j++) {
                const int f = tid + 256 * j, row = f >> 4, c4 = f & 15;
                cp_async16(sbase + vboff + (uint32_t)((st * VST_F + row * VPIT + c4 * 4) * 4),
                           vp + row * DH + c4 * 4);
            }
            cp_commit();
            cp_wait_group<1>();
        } else {
            cp_wait_group<0>();
        }
        __syncthreads();

        const float* Kst = Kb + (kt & 1) * KST_F;
        const float* Vst = Vb + (kt & 1) * VST_F;

        // ---- S = (Q K^T) 3xTF32, ALU-free inner loop ----
        float s[8][4];
#pragma unroll
        for (int u = 0; u < 8; u++)
#pragma unroll
            for (int r = 0; r < 4; r++) s[u][r] = 0.f;

#pragma unroll
        for (int kc = 0; kc < 8; kc++) {
#pragma unroll
            for (int u = 0; u < 8; u++) {
                const int kr = (u * 8 + g8) * KPIT + 2 * (kc * 8 + q);
                const float2 k0 = *(const float2*)&Kst[kr];
                const float2 k1 = *(const float2*)&Kst[kr + 8];
                uint32_t bh[2], bl[2];
                bh[0] = __float_as_uint(k0.x); bl[0] = __float_as_uint(k0.y);
                bh[1] = __float_as_uint(k1.x); bl[1] = __float_as_uint(k1.y);
                mma_tf32(s[u], qh[kc], bh);
                mma_tf32(s[u], qh[kc], bl);
                mma_tf32(s[u], ql[kc], bh);
            }
        }

#pragma unroll
        for (int u = 0; u < 8; u++)
#pragma unroll
            for (int r = 0; r < 4; r++) s[u][r] *= 0.125f;

        if (kt >= 2 * qi) {
            const int cb = kt * 64;
#pragma unroll
            for (int u = 0; u < 8; u++) {
                const int c = cb + u * 8 + 2 * q;
                if (c     > row0) s[u][0] = -1e30f;
                if (c + 1 > row0) s[u][1] = -1e30f;
                if (c     > row1) s[u][2] = -1e30f;
                if (c + 1 > row1) s[u][3] = -1e30f;
            }
        }

        // ---- online softmax ----
        float tm0 = -1e30f, tm1 = -1e30f;
#pragma unroll
        for (int u = 0; u < 8; u++) {
            tm0 = fmaxf(tm0, fmaxf(s[u][0], s[u][1]));
            tm1 = fmaxf(tm1, fmaxf(s[u][2], s[u][3]));
        }
        tm0 = fmaxf(tm0, __shfl_xor_sync(0xffffffffu, tm0, 1));
        tm0 = fmaxf(tm0, __shfl_xor_sync(0xffffffffu, tm0, 2));
        tm1 = fmaxf(tm1, __shfl_xor_sync(0xffffffffu, tm1, 1));
        tm1 = fmaxf(tm1, __shfl_xor_sync(0xffffffffu, tm1, 2));

        const float mn0 = fmaxf(m0, tm0);
        const float mn1 = fmaxf(m1, tm1);
        const float a0 = __expf(m0 - mn0);
        const float a1 = __expf(m1 - mn1);

        float ps0 = 0.f, ps1 = 0.f;
#pragma unroll
        for (int u = 0; u < 8; u++) {
            const float p00 = __expf(s[u][0] - mn0);
            const float p01 = __expf(s[u][1] - mn0);
            const float p10 = __expf(s[u][2] - mn1);
            const float p11 = __expf(s[u][3] - mn1);
            ps0 += p00 + p01;
            ps1 += p10 + p11;
            *(float2*)&QP[(wm + g8) * QPIT + u * 8 + 2 * q]     = make_float2(p00, p01);
            *(float2*)&QP[(wm + g8 + 8) * QPIT + u * 8 + 2 * q] = make_float2(p10, p11);
        }
        ps0 += __shfl_xor_sync(0xffffffffu, ps0, 1);
        ps0 += __shfl_xor_sync(0xffffffffu, ps0, 2);
        ps1 += __shfl_xor_sync(0xffffffffu, ps1, 1);
        ps1 += __shfl_xor_sync(0xffffffffu, ps1, 2);

        l0 = l0 * a0 + ps0;
        l1 = l1 * a1 + ps1;
        m0 = mn0;
        m1 = mn1;
#pragma unroll
        for (int u = 0; u < 8; u++) {
            o[u][0] *= a0; o[u][1] *= a0;
            o[u][2] *= a1; o[u][3] *= a1;
        }
        __syncwarp();

        // ---- O += P @ V (1xTF32; V already tf32-rounded — no cvt) ----
#pragma unroll
        for (int kc = 0; kc < 8; kc++) {
            uint32_t a[4];
            a[0] = f2tf32(QP[(wm + g8) * QPIT + kc * 8 + q]);
            a[1] = f2tf32(QP[(wm + g8 + 8) * QPIT + kc * 8 + q]);
            a[2] = f2tf32(QP[(wm + g8) * QPIT + kc * 8 + q + 4]);
            a[3] = f2tf32(QP[(wm + g8 + 8) * QPIT + kc * 8 + q + 4]);
#pragma unroll
            for (int u = 0; u < 8; u++) {
                uint32_t b[2];
                b[0] = __float_as_uint(Vst[(kc * 8 + q) * VPIT + u * 8 + g8]);
                b[1] = __float_as_uint(Vst[(kc * 8 + q + 4) * VPIT + u * 8 + g8]);
                mma_tf32(o[u], a, b);
            }
        }
    }

    // ---- epilogue: normalize, write pre-split Y for the out-projection ----
    const int b = bh >> 4, h = bh & 15;
    const float i0 = 1.0f / l0;
    const float i1 = 1.0f / l1;
    float* Y0 = g_Ys + 2 * (((size_t)b * S_LEN + row0) * EMB + h * DH);
    float* Y1 = g_Ys + 2 * (((size_t)b * S_LEN + row1) * EMB + h * DH);
#pragma unroll
    for (int u = 0; u < 8; u++) {
        const int c = u * 8 + 2 * q;
        const float y0 = o[u][0] * i0, y1 = o[u][1] * i0;
        const float y2 = o[u][2] * i1, y3 = o[u][3] * i1;
        const float h0 = rtf(y0), h1 = rtf(y1), h2 = rtf(y2), h3 = rtf(y3);
        *(float4*)&Y0[2 * c] = make_float4(h0, rtf(y0 - h0), h1, rtf(y1 - h1));
        *(float4*)&Y1[2 * c] = make_float4(h2, rtf(y2 - h2), h3, rtf(y3 - h3));
    }
}

// ---------------------------------------------------------------------------
extern "C" void kernel_launch(void* const* d_in, const int* in_sizes, int n_in,
                              void* d_out, int out_size)
{
    (void)in_sizes; (void)n_in; (void)out_size;
    const float* x  = (const float*)d_in[0];
    const float* Wq = (const float*)d_in[1];
    const float* Wk = (const float*)d_in[2];
    const float* Wv = (const float*)d_in[3];
    const float* Wo = (const float*)d_in[4];
    float* out = (float*)d_out;

    static bool attr_done = false;       // idempotent setup (not a work guard)
    static float4* p_Xs = nullptr;
    static float4* p_Ws = nullptr;
    if (!attr_done) {
        cudaFuncSetAttribute(gemm_ps<true>,
                             cudaFuncAttributeMaxDynamicSharedMemorySize, PSGSMEM);
        cudaFuncSetAttribute(gemm_ps<false>,
                             cudaFuncAttributeMaxDynamicSharedMemorySize, PSGSMEM);
        cudaFuncSetAttribute(flash_mma,
                             cudaFuncAttributeMaxDynamicSharedMemorySize, FLASH_SMEM);
        cudaGetSymbolAddress((void**)&p_Xs, g_Xs);
        cudaGetSymbolAddress((void**)&p_Ws, g_Ws);
        attr_done = true;
    }

    // 0) pre-split X and weights into (hi,lo) pairs
    split_tf32<<<8192, 256>>>((const float4*)x,  p_Xs,           2097152);
    split_tf32<<<1024, 256>>>((const float4*)Wq, p_Ws,            262144);
    split_tf32<<<1024, 256>>>((const float4*)Wk, p_Ws + 524288,   262144);
    split_tf32<<<1024, 256>>>((const float4*)Wv, p_Ws + 1048576,  262144);
    split_tf32<<<1024, 256>>>((const float4*)Wo, p_Ws + 1572864,  262144);
    // 1) QKV projections (pure-HMMA inner loop)
    gemm_ps<true><<<dim3(64, 8, 3), 256, PSGSMEM>>>(nullptr);
    // 2) Causal flash attention (pre-split K, rounded V)
    flash_mma<<<dim3(16, BATCH * NH), 256, FLASH_SMEM>>>();
    // 3) Output projection
    gemm_ps<false><<<dim3(64, 8), 256, PSGSMEM>>>(out);
}

// round 7
// speedup vs baseline: 1.2338x; 1.2338x over previous
#include <cuda_runtime.h>
#include <cstdint>

#define BATCH 4
#define S_LEN 2048
#define EMB   1024
#define NH    16
#define DH    64

// Scratch (allocation-free rule: __device__ globals)
__device__ float g_Ws[8388608];    // Wq,Wk,Wv,Wo pre-split (hi,lo), 2M floats each
__device__ float g_Q [8388608];    // raw fp32 [B,H,S,Dh]
__device__ float g_K [8388608];    // raw fp32 [B,H,S,Dh]
__device__ float g_V [8388608];    // tf32-rounded [B,H,S,Dh]
__device__ float g_Y [8388608];    // merged heads raw [B,S,E]

// ===========================================================================
// Helpers
// ===========================================================================
__device__ __forceinline__ uint32_t smem_u32(const void* p) {
    uint32_t a;
    asm("{ .reg .u64 t; cvta.to.shared.u64 t, %1; cvt.u32.u64 %0, t; }"
        : "=r"(a) : "l"(p));
    return a;
}
__device__ __forceinline__ void cp_async16(uint32_t s, const void* g) {
    asm volatile("cp.async.cg.shared.global [%0], [%1], 16;" :: "r"(s), "l"(g));
}
__device__ __forceinline__ void cp_commit() {
    asm volatile("cp.async.commit_group;" ::: "memory");
}
template <int N>
__device__ __forceinline__ void cp_wait_group() {
    asm volatile("cp.async.wait_group %0;" :: "n"(N) : "memory");
}
__device__ __forceinline__ void mma_tf32(float* c, const uint32_t* a, const uint32_t* b) {
    asm volatile(
        "mma.sync.aligned.m16n8k8.row.col.f32.tf32.tf32.f32 "
        "{%0,%1,%2,%3}, {%4,%5,%6,%7}, {%8,%9}, {%0,%1,%2,%3};"
        : "+f"(c[0]), "+f"(c[1]), "+f"(c[2]), "+f"(c[3])
        : "r"(a[0]), "r"(a[1]), "r"(a[2]), "r"(a[3]), "r"(b[0]), "r"(b[1]));
}
__device__ __forceinline__ uint32_t f2tf32(float x) {
    uint32_t r;
    asm("cvt.rna.tf32.f32 %0, %1;" : "=r"(r) : "f"(x));
    return r;
}
__device__ __forceinline__ float rtf(float x) {
    return __uint_as_float(f2tf32(x));
}

// ===========================================================================
// Pre-split weights: w -> interleaved (tf32 hi, tf32 lo) pairs.
// ===========================================================================
__global__ __launch_bounds__(256) void split_tf32(const float4* __restrict__ src,
                                                  float4* __restrict__ dst, int n4)
{
    const int i = blockIdx.x * 256 + threadIdx.x;
    if (i >= n4) return;
    const float4 v = src[i];
    const float hx = rtf(v.x), hy = rtf(v.y), hz = rtf(v.z), hw = rtf(v.w);
    dst[2 * i]     = make_float4(hx, rtf(v.x - hx), hy, rtf(v.y - hy));
    dst[2 * i + 1] = make_float4(hz, rtf(v.z - hz), hw, rtf(v.w - hw));
}

// ===========================================================================
// Hybrid 3xTF32 GEMM: C[M,N] = A[M,K] * W[N,K]^T.
// A raw fp32 (split in-loop, 24 ALU/ks); W pre-split (hi,lo) — zero B ALU.
// BM=128, BN=128, BK=32; stage = 55296 B, 2 stages = 110592 B (2 CTAs/SM).
// ===========================================================================
#define APIT 36
#define BPIT 72
#define HSTAGE (128 * APIT + 128 * BPIT)     // 13824 floats per stage
#define HGSMEM (2 * HSTAGE * 4)              // 110592 bytes

template <bool SCATTER>
__global__ __launch_bounds__(256) void gemm_hs(
    const float* __restrict__ Ain, float* __restrict__ outp)
{
    const float* Ag;
    const float* Bg;
    if (SCATTER) {
        Ag = Ain;
        Bg = g_Ws + (size_t)blockIdx.z * 2097152;
    } else {
        Ag = g_Y;
        Bg = g_Ws + 6291456;
    }

    extern __shared__ __align__(16) float sm[];
    const int tid  = threadIdx.x;
    const int wid  = tid >> 5;
    const int lane = tid & 31;
    const int m0   = blockIdx.x * 128;
    const int n0   = blockIdx.y * 128;
    const int wm   = (wid >> 1) * 32;
    const int wn   = (wid & 1) * 64;
    const int q    = lane & 3;
    const int g8   = lane >> 2;

    const int arow = tid >> 3, ac4 = tid & 7;     // A: 4 f4/thread
    const int brow = tid >> 4, bc4 = tid & 15;    // B: 8 f4/thread

    const uint32_t sbase = smem_u32(sm);
    const float* Abase = Ag + (size_t)m0 * EMB;
    const float* Bbase = Bg + (size_t)n0 * 2048;

    // preload chunk 0
#pragma unroll
    for (int j = 0; j < 4; j++) {
        const int row = arow + 32 * j;
        cp_async16(sbase + (uint32_t)((row * APIT + ac4 * 4) * 4),
                   Abase + (size_t)row * EMB + ac4 * 4);
    }
#pragma unroll
    for (int j = 0; j < 8; j++) {
        const int row = brow + 16 * j;
        cp_async16(sbase + (uint32_t)((128 * APIT + row * BPIT + bc4 * 4) * 4),
                   Bbase + (size_t)row * 2048 + bc4 * 4);
    }
    cp_commit();

    float acc[2][8][4];
#pragma unroll
    for (int t = 0; t < 2; t++)
#pragma unroll
        for (int u = 0; u < 8; u++)
#pragma unroll
            for (int r = 0; r < 4; r++) acc[t][u][r] = 0.f;

    for (int kt = 0; kt < 32; kt++) {
        if (kt + 1 < 32) {
            const uint32_t st = ((kt + 1) & 1) * (uint32_t)(HSTAGE * 4);
            const float* ap = Abase + (size_t)(kt + 1) * 32;
            const float* bp = Bbase + (size_t)(kt + 1) * 64;
#pragma unroll
            for (int j = 0; j < 4; j++) {
                const int row = arow + 32 * j;
                cp_async16(sbase + st + (uint32_t)((row * APIT + ac4 * 4) * 4),
                           ap + (size_t)row * EMB + ac4 * 4);
            }
#pragma unroll
            for (int j = 0; j < 8; j++) {
                const int row = brow + 16 * j;
                cp_async16(sbase + st + (uint32_t)((128 * APIT + row * BPIT + bc4 * 4) * 4),
                           bp + (size_t)row * 2048 + bc4 * 4);
            }
            cp_commit();
            cp_wait_group<1>();
        } else {
            cp_wait_group<0>();
        }
        __syncthreads();

        const float* As = sm + (kt & 1) * HSTAGE;
        const float* Bs = As + 128 * APIT;

#pragma unroll
        for (int ks = 0; ks < 4; ks++) {
            const int k = ks * 8;
            uint32_t ah[2][4], al[2][4];
#pragma unroll
            for (int t = 0; t < 2; t++) {
                const int r0 = wm + t * 16 + g8;
                float af[4];
                af[0] = As[r0 * APIT + k + q];
                af[1] = As[(r0 + 8) * APIT + k + q];
                af[2] = As[r0 * APIT + k + q + 4];
                af[3] = As[(r0 + 8) * APIT + k + q + 4];
#pragma unroll
                for (int r = 0; r < 4; r++) {
                    ah[t][r] = f2tf32(af[r]);
                    al[t][r] = f2tf32(af[r] - __uint_as_float(ah[t][r]));
                }
            }
#pragma unroll
            for (int u = 0; u < 8; u++) {
                const int nb = (wn + u * 8 + g8) * BPIT + 2 * (k + q);
                const float2 b0 = *(const float2*)&Bs[nb];
                const float2 b1 = *(const float2*)&Bs[nb + 8];
                uint32_t bh[2], bl[2];
                bh[0] = __float_as_uint(b0.x); bl[0] = __float_as_uint(b0.y);
                bh[1] = __float_as_uint(b1.x); bl[1] = __float_as_uint(b1.y);
#pragma unroll
                for (int t = 0; t < 2; t++) {
                    mma_tf32(acc[t][u], ah[t], bh);
                    mma_tf32(acc[t][u], ah[t], bl);
                    mma_tf32(acc[t][u], al[t], bh);
                }
            }
        }
        __syncthreads();
    }

    // ---- epilogue ----
    const int z = SCATTER ? blockIdx.z : 3;
#pragma unroll
    for (int t = 0; t < 2; t++) {
#pragma unroll
        for (int u = 0; u < 8; u++) {
            const int m = m0 + wm + t * 16 + g8;
            const int n = n0 + wn + u * 8 + q * 2;
#pragma unroll
            for (int hh = 0; hh < 2; hh++) {
                const int mm = m + hh * 8;
                const float v0 = acc[t][u][hh * 2];
                const float v1 = acc[t][u][hh * 2 + 1];
                if (SCATTER) {
                    const int bb = mm >> 11, s = mm & 2047;
                    const int h = n >> 6, d0 = n & 63;
                    const size_t e = (((size_t)bb * NH + h) * S_LEN + s) * DH + d0;
                    if (z == 0)      *(float2*)(g_Q + e) = make_float2(v0, v1);
                    else if (z == 1) *(float2*)(g_K + e) = make_float2(v0, v1);
                    else             *(float2*)(g_V + e) = make_float2(rtf(v0), rtf(v1));
                } else {
                    *(float2*)(outp + (size_t)mm * EMB + n) = make_float2(v0, v1);
                }
            }
        }
    }
}

// ===========================================================================
// mma.sync flash attention, causal (round-5 proven structure, 106 KB smem,
// 2 CTAs/SM). QK^T 3xTF32 with in-loop K split; PV 1xTF32 (V pre-rounded).
// ===========================================================================
#define QPIT 68
#define KPIT 68
#define VPIT 72
#define QP_F   (128 * QPIT)
#define KST_F  (64 * KPIT)
#define VST_F  (64 * VPIT)
#define FLASH_SMEM ((QP_F + 2 * KST_F + 2 * VST_F) * 4)   // 106496 B

__global__ __launch_bounds__(256) void flash_mma()
{
    const int qi = blockIdx.x;
    const int bh = blockIdx.y;

    extern __shared__ __align__(16) float sm[];
    float* QP = sm;
    float* Kb = sm + QP_F;
    float* Vb = Kb + 2 * KST_F;

    const int tid  = threadIdx.x;
    const int wid  = tid >> 5;
    const int lane = tid & 31;
    const int g8   = lane >> 2;
    const int q    = lane & 3;
    const int wm   = wid * 16;

    const float* Qg = g_Q + ((size_t)bh * S_LEN + (size_t)qi * 128) * DH;
    const float* Kg = g_K + (size_t)bh * S_LEN * DH;
    const float* Vg = g_V + (size_t)bh * S_LEN * DH;

    const uint32_t sbase = smem_u32(sm);
    const uint32_t kboff = (uint32_t)(QP_F * 4);
    const uint32_t vboff = (uint32_t)((QP_F + 2 * KST_F) * 4);

#pragma unroll
    for (int j = 0; j < 8; j++) {
        const int f = tid + 256 * j, row = f >> 4, c4 = f & 15;
        cp_async16(sbase + (uint32_t)((row * QPIT + c4 * 4) * 4),
                   Qg + row * DH + c4 * 4);
    }
    cp_commit();
#pragma unroll
    for (int j = 0; j < 4; j++) {
        const int f = tid + 256 * j, row = f >> 4, c4 = f & 15;
        cp_async16(sbase + kboff + (uint32_t)((row * KPIT + c4 * 4) * 4),
                   Kg + row * DH + c4 * 4);
        cp_async16(sbase + vboff + (uint32_t)((row * VPIT + c4 * 4) * 4),
                   Vg + row * DH + c4 * 4);
    }
    cp_commit();

    cp_wait_group<1>();
    __syncthreads();

    uint32_t qh[8][4], ql[8][4];
#pragma unroll
    for (int kc = 0; kc < 8; kc++) {
        const float f0 = QP[(wm + g8) * QPIT + kc * 8 + q];
        const float f1 = QP[(wm + g8 + 8) * QPIT + kc * 8 + q];
        const float f2 = QP[(wm + g8) * QPIT + kc * 8 + q + 4];
        const float f3 = QP[(wm + g8 + 8) * QPIT + kc * 8 + q + 4];
        qh[kc][0] = f2tf32(f0); ql[kc][0] = f2tf32(f0 - __uint_as_float(qh[kc][0]));
        qh[kc][1] = f2tf32(f1); ql[kc][1] = f2tf32(f1 - __uint_as_float(qh[kc][1]));
        qh[kc][2] = f2tf32(f2); ql[kc][2] = f2tf32(f2 - __uint_as_float(qh[kc][2]));
        qh[kc][3] = f2tf32(f3); ql[kc][3] = f2tf32(f3 - __uint_as_float(qh[kc][3]));
    }
    __syncthreads();

    float m0 = -1e30f, m1 = -1e30f, l0 = 0.f, l1 = 0.f;
    float o[8][4];
#pragma unroll
    for (int u = 0; u < 8; u++)
#pragma unroll
        for (int r = 0; r < 4; r++) o[u][r] = 0.f;

    const int row0 = qi * 128 + wm + g8;
    const int row1 = row0 + 8;
    const int last = 2 * qi + 1;

    for (int kt = 0; kt <= last; kt++) {
        if (kt < last) {
            const int st = (kt + 1) & 1;
            const float* kp = Kg + (size_t)(kt + 1) * 64 * DH;
            const float* vp = Vg + (size_t)(kt + 1) * 64 * DH;
#pragma unroll
            for (int j = 0; j < 4; j++) {
                const int f = tid + 256 * j, row = f >> 4, c4 = f & 15;
                cp_async16(sbase + kboff + (uint32_t)((st * KST_F + row * KPIT + c4 * 4) * 4),
                           kp + row * DH + c4 * 4);
                cp_async16(sbase + vboff + (uint32_t)((st * VST_F + row * VPIT + c4 * 4) * 4),
                           vp + row * DH + c4 * 4);
            }
            cp_commit();
            cp_wait_group<1>();
        } else {
            cp_wait_group<0>();
        }
        __syncthreads();

        const float* Kst = Kb + (kt & 1) * KST_F;
        const float* Vst = Vb + (kt & 1) * VST_F;

        float s[8][4];
#pragma unroll
        for (int u = 0; u < 8; u++)
#pragma unroll
            for (int r = 0; r < 4; r++) s[u][r] = 0.f;

#pragma unroll
        for (int kc = 0; kc < 8; kc++) {
#pragma unroll
            for (int u = 0; u < 8; u++) {
                const float bf0 = Kst[(u * 8 + g8) * KPIT + kc * 8 + q];
                const float bf1 = Kst[(u * 8 + g8) * KPIT + kc * 8 + q + 4];
                uint32_t bh[2], bl[2];
                bh[0] = f2tf32(bf0);
                bh[1] = f2tf32(bf1);
                bl[0] = f2tf32(bf0 - __uint_as_float(bh[0]));
                bl[1] = f2tf32(bf1 - __uint_as_float(bh[1]));
                mma_tf32(s[u], qh[kc], bh);
                mma_tf32(s[u], qh[kc], bl);
                mma_tf32(s[u], ql[kc], bh);
            }
        }

#pragma unroll
        for (int u = 0; u < 8; u++)
#pragma unroll
            for (int r = 0; r < 4; r++) s[u][r] *= 0.125f;

        if (kt >= 2 * qi) {
            const int cb = kt * 64;
#pragma unroll
            for (int u = 0; u < 8; u++) {
                const int c = cb + u * 8 + 2 * q;
                if (c     > row0) s[u][0] = -1e30f;
                if (c + 1 > row0) s[u][1] = -1e30f;
                if (c     > row1) s[u][2] = -1e30f;
                if (c + 1 > row1) s[u][3] = -1e30f;
            }
        }

        float tm0 = -1e30f, tm1 = -1e30f;
#pragma unroll
        for (int u = 0; u < 8; u++) {
            tm0 = fmaxf(tm0, fmaxf(s[u][0], s[u][1]));
            tm1 = fmaxf(tm1, fmaxf(s[u][2], s[u][3]));
        }
        tm0 = fmaxf(tm0, __shfl_xor_sync(0xffffffffu, tm0, 1));
        tm0 = fmaxf(tm0, __shfl_xor_sync(0xffffffffu, tm0, 2));
        tm1 = fmaxf(tm1, __shfl_xor_sync(0xffffffffu, tm1, 1));
        tm1 = fmaxf(tm1, __shfl_xor_sync(0xffffffffu, tm1, 2));

        const float mn0 = fmaxf(m0, tm0);
        const float mn1 = fmaxf(m1, tm1);
        const float a0 = __expf(m0 - mn0);
        const float a1 = __expf(m1 - mn1);

        float ps0 = 0.f, ps1 = 0.f;
#pragma unroll
        for (int u = 0; u < 8; u++) {
            const float p00 = __expf(s[u][0] - mn0);
            const float p01 = __expf(s[u][1] - mn0);
            const float p10 = __expf(s[u][2] - mn1);
            const float p11 = __expf(s[u][3] - mn1);
            ps0 += p00 + p01;
            ps1 += p10 + p11;
            *(float2*)&QP[(wm + g8) * QPIT + u * 8 + 2 * q]     = make_float2(p00, p01);
            *(float2*)&QP[(wm + g8 + 8) * QPIT + u * 8 + 2 * q] = make_float2(p10, p11);
        }
        ps0 += __shfl_xor_sync(0xffffffffu, ps0, 1);
        ps0 += __shfl_xor_sync(0xffffffffu, ps0, 2);
        ps1 += __shfl_xor_sync(0xffffffffu, ps1, 1);
        ps1 += __shfl_xor_sync(0xffffffffu, ps1, 2);

        l0 = l0 * a0 + ps0;
        l1 = l1 * a1 + ps1;
        m0 = mn0;
        m1 = mn1;
#pragma unroll
        for (int u = 0; u < 8; u++) {
            o[u][0] *= a0; o[u][1] *= a0;
            o[u][2] *= a1; o[u][3] *= a1;
        }
        __syncwarp();

#pragma unroll
        for (int kc = 0; kc < 8; kc++) {
            uint32_t a[4];
            a[0] = f2tf32(QP[(wm + g8) * QPIT + kc * 8 + q]);
            a[1] = f2tf32(QP[(wm + g8 + 8) * QPIT + kc * 8 + q]);
            a[2] = f2tf32(QP[(wm + g8) * QPIT + kc * 8 + q + 4]);
            a[3] = f2tf32(QP[(wm + g8 + 8) * QPIT + kc * 8 + q + 4]);
#pragma unroll
            for (int u = 0; u < 8; u++) {
                uint32_t b[2];
                b[0] = __float_as_uint(Vst[(kc * 8 + q) * VPIT + u * 8 + g8]);
                b[1] = __float_as_uint(Vst[(kc * 8 + q + 4) * VPIT + u * 8 + g8]);
                mma_tf32(o[u], a, b);
            }
        }
    }

    // ---- epilogue: normalize, write merged-head raw Y ----
    const int b = bh >> 4, h = bh & 15;
    const float i0 = 1.0f / l0;
    const float i1 = 1.0f / l1;
    float* Y0 = g_Y + ((size_t)b * S_LEN + row0) * EMB + h * DH;
    float* Y1 = g_Y + ((size_t)b * S_LEN + row1) * EMB + h * DH;
#pragma unroll
    for (int u = 0; u < 8; u++) {
        const int c = u * 8 + 2 * q;
        *(float2*)&Y0[c] = make_float2(o[u][0] * i0, o[u][1] * i0);
        *(float2*)&Y1[c] = make_float2(o[u][2] * i1, o[u][3] * i1);
    }
}

// ---------------------------------------------------------------------------
extern "C" void kernel_launch(void* const* d_in, const int* in_sizes, int n_in,
                              void* d_out, int out_size)
{
    (void)in_sizes; (void)n_in; (void)out_size;
    const float* x  = (const float*)d_in[0];
    const float* Wq = (const float*)d_in[1];
    const float* Wk = (const float*)d_in[2];
    const float* Wv = (const float*)d_in[3];
    const float* Wo = (const float*)d_in[4];
    float* out = (float*)d_out;

    static bool attr_done = false;       // idempotent setup (not a work guard)
    static float4* p_Ws = nullptr;
    if (!attr_done) {
        cudaFuncSetAttribute(gemm_hs<true>,
                             cudaFuncAttributeMaxDynamicSharedMemorySize, HGSMEM);
        cudaFuncSetAttribute(gemm_hs<false>,
                             cudaFuncAttributeMaxDynamicSharedMemorySize, HGSMEM);
        cudaFuncSetAttribute(flash_mma,
                             cudaFuncAttributeMaxDynamicSharedMemorySize, FLASH_SMEM);
        cudaGetSymbolAddress((void**)&p_Ws, g_Ws);
        attr_done = true;
    }

    // 0) pre-split weights only (small, ~7 us total)
    split_tf32<<<1024, 256>>>((const float4*)Wq, p_Ws,            262144);
    split_tf32<<<1024, 256>>>((const float4*)Wk, p_Ws + 524288,   262144);
    split_tf32<<<1024, 256>>>((const float4*)Wv, p_Ws + 1048576,  262144);
    split_tf32<<<1024, 256>>>((const float4*)Wo, p_Ws + 1572864,  262144);
    // 1) QKV projections (hybrid split: A in-loop, W pre-split)
    gemm_hs<true><<<dim3(64, 8, 3), 256, HGSMEM>>>(x, nullptr);
    // 2) Causal flash attention (round-5 structure, V pre-rounded)
    flash_mma<<<dim3(16, BATCH * NH), 256, FLASH_SMEM>>>();
    // 3) Output projection
    gemm_hs<false><<<dim3(64, 8), 256, HGSMEM>>>(nullptr, out);
}

// round 12
// speedup vs baseline: 1.2888x; 1.0446x over previous
#include <cuda_runtime.h>
#include <cstdint>

#define BATCH 4
#define S_LEN 2048
#define EMB   1024
#define NH    16
#define DH    64

// Scratch (allocation-free rule: __device__ globals)
__device__ float g_Ws[8388608];    // Wq,Wk,Wv,Wo pre-split (hi,lo), 2M floats each
__device__ float g_Q [8388608];    // raw fp32 [B,H,S,Dh]
__device__ float g_K [8388608];    // raw fp32 [B,H,S,Dh]
__device__ float g_V [8388608];    // tf32-rounded [B,H,S,Dh]
__device__ float g_Y [8388608];    // merged heads raw [B,S,E]

// ===========================================================================
// Helpers
// ===========================================================================
__device__ __forceinline__ uint32_t smem_u32(const void* p) {
    uint32_t a;
    asm("{ .reg .u64 t; cvta.to.shared.u64 t, %1; cvt.u32.u64 %0, t; }"
        : "=r"(a) : "l"(p));
    return a;
}
__device__ __forceinline__ void cp_async16(uint32_t s, const void* g) {
    asm volatile("cp.async.cg.shared.global [%0], [%1], 16;" :: "r"(s), "l"(g));
}
__device__ __forceinline__ void cp_commit() {
    asm volatile("cp.async.commit_group;" ::: "memory");
}
template <int N>
__device__ __forceinline__ void cp_wait_group() {
    asm volatile("cp.async.wait_group %0;" :: "n"(N) : "memory");
}
__device__ __forceinline__ void mma_tf32(float* c, const uint32_t* a, const uint32_t* b) {
    asm volatile(
        "mma.sync.aligned.m16n8k8.row.col.f32.tf32.tf32.f32 "
        "{%0,%1,%2,%3}, {%4,%5,%6,%7}, {%8,%9}, {%0,%1,%2,%3};"
        : "+f"(c[0]), "+f"(c[1]), "+f"(c[2]), "+f"(c[3])
        : "r"(a[0]), "r"(a[1]), "r"(a[2]), "r"(a[3]), "r"(b[0]), "r"(b[1]));
}
__device__ __forceinline__ uint32_t f2tf32(float x) {
    uint32_t r;
    asm("cvt.rna.tf32.f32 %0, %1;" : "=r"(r) : "f"(x));
    return r;
}
__device__ __forceinline__ float rtf(float x) {
    return __uint_as_float(f2tf32(x));
}

// ===========================================================================
// Pre-split weights: w -> interleaved (tf32 hi, tf32 lo) fp32 pairs.
// ===========================================================================
__global__ __launch_bounds__(256) void split_tf32(const float4* __restrict__ src,
                                                  float4* __restrict__ dst, int n4)
{
    const int i = blockIdx.x * 256 + threadIdx.x;
    if (i >= n4) return;
    const float4 v = src[i];
    const float hx = rtf(v.x), hy = rtf(v.y), hz = rtf(v.z), hw = rtf(v.w);
    dst[2 * i]     = make_float4(hx, rtf(v.x - hx), hy, rtf(v.y - hy));
    dst[2 * i + 1] = make_float4(hz, rtf(v.z - hz), hw, rtf(v.w - hw));
}

// ===========================================================================
// Hybrid 3xTF32 GEMM (round-7 PROVEN; race-free: trailing barrier present).
// A raw fp32 (split in-loop); W pre-split (hi,lo) — zero B-side ALU.
// BM=128, BN=128, BK=32; stage = 55296 B, 2 stages = 110592 B (2 CTAs/SM).
// ===========================================================================
#define APIT 36
#define BPIT 72
#define HSTAGE (128 * APIT + 128 * BPIT)     // 13824 floats per stage
#define HGSMEM (2 * HSTAGE * 4)              // 110592 bytes

template <bool SCATTER>
__global__ __launch_bounds__(256, 2) void gemm_hs(
    const float* __restrict__ Ain, float* __restrict__ outp)
{
    const float* Ag;
    const float* Bg;
    if (SCATTER) {
        Ag = Ain;
        Bg = g_Ws + (size_t)blockIdx.z * 2097152;
    } else {
        Ag = g_Y;
        Bg = g_Ws + 6291456;
    }

    extern __shared__ __align__(16) float sm[];
    const int tid  = threadIdx.x;
    const int wid  = tid >> 5;
    const int lane = tid & 31;
    const int m0   = blockIdx.x * 128;
    const int n0   = blockIdx.y * 128;
    const int wm   = (wid >> 1) * 32;
    const int wn   = (wid & 1) * 64;
    const int q    = lane & 3;
    const int g8   = lane >> 2;

    const int arow = tid >> 3, ac4 = tid & 7;     // A: 4 f4/thread
    const int brow = tid >> 4, bc4 = tid & 15;    // B: 8 f4/thread

    const uint32_t sbase = smem_u32(sm);
    const float* Abase = Ag + (size_t)m0 * EMB;
    const float* Bbase = Bg + (size_t)n0 * 2048;

    // preload chunk 0
#pragma unroll
    for (int j = 0; j < 4; j++) {
        const int row = arow + 32 * j;
        cp_async16(sbase + (uint32_t)((row * APIT + ac4 * 4) * 4),
                   Abase + (size_t)row * EMB + ac4 * 4);
    }
#pragma unroll
    for (int j = 0; j < 8; j++) {
        const int row = brow + 16 * j;
        cp_async16(sbase + (uint32_t)((128 * APIT + row * BPIT + bc4 * 4) * 4),
                   Bbase + (size_t)row * 2048 + bc4 * 4);
    }
    cp_commit();

    float acc[2][8][4];
#pragma unroll
    for (int t = 0; t < 2; t++)
#pragma unroll
        for (int u = 0; u < 8; u++)
#pragma unroll
            for (int r = 0; r < 4; r++) acc[t][u][r] = 0.f;

    for (int kt = 0; kt < 32; kt++) {
        if (kt + 1 < 32) {
            const uint32_t st = ((kt + 1) & 1) * (uint32_t)(HSTAGE * 4);
            const float* ap = Abase + (size_t)(kt + 1) * 32;
            const float* bp = Bbase + (size_t)(kt + 1) * 64;
#pragma unroll
            for (int j = 0; j < 4; j++) {
                const int row = arow + 32 * j;
                cp_async16(sbase + st + (uint32_t)((row * APIT + ac4 * 4) * 4),
                           ap + (size_t)row * EMB + ac4 * 4);
            }
#pragma unroll
            for (int j = 0; j < 8; j++) {
                const int row = brow + 16 * j;
                cp_async16(sbase + st + (uint32_t)((128 * APIT + row * BPIT + bc4 * 4) * 4),
                           bp + (size_t)row * 2048 + bc4 * 4);
            }
            cp_commit();
            cp_wait_group<1>();
        } else {
            cp_wait_group<0>();
        }
        __syncthreads();

        const float* As = sm + (kt & 1) * HSTAGE;
        const float* Bs = As + 128 * APIT;

#pragma unroll
        for (int ks = 0; ks < 4; ks++) {
            const int k = ks * 8;
            uint32_t ah[2][4], al[2][4];
#pragma unroll
            for (int t = 0; t < 2; t++) {
                const int r0 = wm + t * 16 + g8;
                float af[4];
                af[0] = As[r0 * APIT + k + q];
                af[1] = As[(r0 + 8) * APIT + k + q];
                af[2] = As[r0 * APIT + k + q + 4];
                af[3] = As[(r0 + 8) * APIT + k + q + 4];
#pragma unroll
                for (int r = 0; r < 4; r++) {
                    ah[t][r] = f2tf32(af[r]);
                    al[t][r] = f2tf32(af[r] - __uint_as_float(ah[t][r]));
                }
            }
#pragma unroll
            for (int u = 0; u < 8; u++) {
                const int nb = (wn + u * 8 + g8) * BPIT + 2 * (k + q);
                const float2 b0 = *(const float2*)&Bs[nb];
                const float2 b1 = *(const float2*)&Bs[nb + 8];
                uint32_t bh[2], bl[2];
                bh[0] = __float_as_uint(b0.x); bl[0] = __float_as_uint(b0.y);
                bh[1] = __float_as_uint(b1.x); bl[1] = __float_as_uint(b1.y);
#pragma unroll
                for (int t = 0; t < 2; t++) {
                    mma_tf32(acc[t][u], ah[t], bh);
                    mma_tf32(acc[t][u], ah[t], bl);
                    mma_tf32(acc[t][u], al[t], bh);
                }
            }
        }
        __syncthreads();    // all reads of this stage done before next overwrite
    }

    // ---- epilogue ----
    const int z = SCATTER ? blockIdx.z : 3;
#pragma unroll
    for (int t = 0; t < 2; t++) {
#pragma unroll
        for (int u = 0; u < 8; u++) {
            const int m = m0 + wm + t * 16 + g8;
            const int n = n0 + wn + u * 8 + q * 2;
#pragma unroll
            for (int hh = 0; hh < 2; hh++) {
                const int mm = m + hh * 8;
                const float v0 = acc[t][u][hh * 2];
                const float v1 = acc[t][u][hh * 2 + 1];
                if (SCATTER) {
                    const int bb = mm >> 11, s = mm & 2047;
                    const int h = n >> 6, d0 = n & 63;
                    const size_t e = (((size_t)bb * NH + h) * S_LEN + s) * DH + d0;
                    if (z == 0)      *(float2*)(g_Q + e) = make_float2(v0, v1);
                    else if (z == 1) *(float2*)(g_K + e) = make_float2(v0, v1);
                    else             *(float2*)(g_V + e) = make_float2(rtf(v0), rtf(v1));
                } else {
                    *(float2*)(outp + (size_t)mm * EMB + n) = make_float2(v0, v1);
                }
            }
        }
    }
}

// ===========================================================================
// Flash attention — 3xTF32 QK, 1xTF32 PV.  RACE FIX: trailing __syncthreads()
// closes the stage-overwrite window (next iteration's cp.async into stage
// kt&1 can no longer race slower warps still reading it).
// LPT grid order + exact Q scale-fold retained. 106 KB smem.
// ===========================================================================
#define QPIT 68
#define KPIT 68
#define VPIT 72
#define QP_F   (128 * QPIT)
#define KST_F  (64 * KPIT)
#define VST_F  (64 * VPIT)
#define FLASH_SMEM ((QP_F + 2 * KST_F + 2 * VST_F) * 4)   // 106496 B

__global__ __launch_bounds__(256) void flash_mma()
{
    const int bh = blockIdx.x;
    const int qi = 15 - blockIdx.y;          // LPT: long jobs first

    extern __shared__ __align__(16) float sm[];
    float* QP = sm;
    float* Kb = sm + QP_F;
    float* Vb = Kb + 2 * KST_F;

    const int tid  = threadIdx.x;
    const int wid  = tid >> 5;
    const int lane = tid & 31;
    const int g8   = lane >> 2;
    const int q    = lane & 3;
    const int wm   = wid * 16;

    const float* Qg = g_Q + ((size_t)bh * S_LEN + (size_t)qi * 128) * DH;
    const float* Kg = g_K + (size_t)bh * S_LEN * DH;
    const float* Vg = g_V + (size_t)bh * S_LEN * DH;

    const uint32_t sbase = smem_u32(sm);
    const uint32_t kboff = (uint32_t)(QP_F * 4);
    const uint32_t vboff = (uint32_t)((QP_F + 2 * KST_F) * 4);

#pragma unroll
    for (int j = 0; j < 8; j++) {
        const int f = tid + 256 * j, row = f >> 4, c4 = f & 15;
        cp_async16(sbase + (uint32_t)((row * QPIT + c4 * 4) * 4),
                   Qg + row * DH + c4 * 4);
    }
    cp_commit();
#pragma unroll
    for (int j = 0; j < 4; j++) {
        const int f = tid + 256 * j, row = f >> 4, c4 = f & 15;
        cp_async16(sbase + kboff + (uint32_t)((row * KPIT + c4 * 4) * 4),
                   Kg + row * DH + c4 * 4);
        cp_async16(sbase + vboff + (uint32_t)((row * VPIT + c4 * 4) * 4),
                   Vg + row * DH + c4 * 4);
    }
    cp_commit();

    cp_wait_group<1>();
    __syncthreads();

    // ---- hoist Q fragments (3xTF32 split; 1/8 scale folded in, exact) ----
    uint32_t qh[8][4], ql[8][4];
#pragma unroll
    for (int kc = 0; kc < 8; kc++) {
        const float f0 = 0.125f * QP[(wm + g8) * QPIT + kc * 8 + q];
        const float f1 = 0.125f * QP[(wm + g8 + 8) * QPIT + kc * 8 + q];
        const float f2 = 0.125f * QP[(wm + g8) * QPIT + kc * 8 + q + 4];
        const float f3 = 0.125f * QP[(wm + g8 + 8) * QPIT + kc * 8 + q + 4];
        qh[kc][0] = f2tf32(f0); ql[kc][0] = f2tf32(f0 - __uint_as_float(qh[kc][0]));
        qh[kc][1] = f2tf32(f1); ql[kc][1] = f2tf32(f1 - __uint_as_float(qh[kc][1]));
        qh[kc][2] = f2tf32(f2); ql[kc][2] = f2tf32(f2 - __uint_as_float(qh[kc][2]));
        qh[kc][3] = f2tf32(f3); ql[kc][3] = f2tf32(f3 - __uint_as_float(qh[kc][3]));
    }
    __syncthreads();

    float m0 = -1e30f, m1 = -1e30f, l0 = 0.f, l1 = 0.f;
    float o[8][4];
#pragma unroll
    for (int u = 0; u < 8; u++)
#pragma unroll
        for (int r = 0; r < 4; r++) o[u][r] = 0.f;

    const int row0 = qi * 128 + wm + g8;
    const int row1 = row0 + 8;
    const int last = 2 * qi + 1;

    for (int kt = 0; kt <= last; kt++) {
        if (kt < last) {
            const int st = (kt + 1) & 1;
            const float* kp = Kg + (size_t)(kt + 1) * 64 * DH;
            const float* vp = Vg + (size_t)(kt + 1) * 64 * DH;
#pragma unroll
            for (int j = 0; j < 4; j++) {
                const int f = tid + 256 * j, row = f >> 4, c4 = f & 15;
                cp_async16(sbase + kboff + (uint32_t)((st * KST_F + row * KPIT + c4 * 4) * 4),
                           kp + row * DH + c4 * 4);
                cp_async16(sbase + vboff + (uint32_t)((st * VST_F + row * VPIT + c4 * 4) * 4),
                           vp + row * DH + c4 * 4);
            }
            cp_commit();
            cp_wait_group<1>();
        } else {
            cp_wait_group<0>();
        }
        __syncthreads();

        const float* Kst = Kb + (kt & 1) * KST_F;
        const float* Vst = Vb + (kt & 1) * VST_F;

        float s[8][4];
#pragma unroll
        for (int u = 0; u < 8; u++)
#pragma unroll
            for (int r = 0; r < 4; r++) s[u][r] = 0.f;

#pragma unroll
        for (int kc = 0; kc < 8; kc++) {
#pragma unroll
            for (int u = 0; u < 8; u++) {
                const float bf0 = Kst[(u * 8 + g8) * KPIT + kc * 8 + q];
                const float bf1 = Kst[(u * 8 + g8) * KPIT + kc * 8 + q + 4];
                uint32_t bh[2], bl[2];
                bh[0] = f2tf32(bf0);
                bh[1] = f2tf32(bf1);
                bl[0] = f2tf32(bf0 - __uint_as_float(bh[0]));
                bl[1] = f2tf32(bf1 - __uint_as_float(bh[1]));
                mma_tf32(s[u], qh[kc], bh);
                mma_tf32(s[u], qh[kc], bl);
                mma_tf32(s[u], ql[kc], bh);
            }
        }

        if (kt >= 2 * qi) {
            const int cb = kt * 64;
#pragma unroll
            for (int u = 0; u < 8; u++) {
                const int c = cb + u * 8 + 2 * q;
                if (c     > row0) s[u][0] = -1e30f;
                if (c + 1 > row0) s[u][1] = -1e30f;
                if (c     > row1) s[u][2] = -1e30f;
                if (c + 1 > row1) s[u][3] = -1e30f;
            }
        }

        float tm0 = -1e30f, tm1 = -1e30f;
#pragma unroll
        for (int u = 0; u < 8; u++) {
            tm0 = fmaxf(tm0, fmaxf(s[u][0], s[u][1]));
            tm1 = fmaxf(tm1, fmaxf(s[u][2], s[u][3]));
        }
        tm0 = fmaxf(tm0, __shfl_xor_sync(0xffffffffu, tm0, 1));
        tm0 = fmaxf(tm0, __shfl_xor_sync(0xffffffffu, tm0, 2));
        tm1 = fmaxf(tm1, __shfl_xor_sync(0xffffffffu, tm1, 1));
        tm1 = fmaxf(tm1, __shfl_xor_sync(0xffffffffu, tm1, 2));

        const float mn0 = fmaxf(m0, tm0);
        const float mn1 = fmaxf(m1, tm1);
        const float a0 = __expf(m0 - mn0);
        const float a1 = __expf(m1 - mn1);

        float ps0 = 0.f, ps1 = 0.f;
#pragma unroll
        for (int u = 0; u < 8; u++) {
            const float p00 = __expf(s[u][0] - mn0);
            const float p01 = __expf(s[u][1] - mn0);
            const float p10 = __expf(s[u][2] - mn1);
            const float p11 = __expf(s[u][3] - mn1);
            ps0 += p00 + p01;
            ps1 += p10 + p11;
            *(float2*)&QP[(wm + g8) * QPIT + u * 8 + 2 * q]     = make_float2(p00, p01);
            *(float2*)&QP[(wm + g8 + 8) * QPIT + u * 8 + 2 * q] = make_float2(p10, p11);
        }
        ps0 += __shfl_xor_sync(0xffffffffu, ps0, 1);
        ps0 += __shfl_xor_sync(0xffffffffu, ps0, 2);
        ps1 += __shfl_xor_sync(0xffffffffu, ps1, 1);
        ps1 += __shfl_xor_sync(0xffffffffu, ps1, 2);

        l0 = l0 * a0 + ps0;
        l1 = l1 * a1 + ps1;
        m0 = mn0;
        m1 = mn1;
#pragma unroll
        for (int u = 0; u < 8; u++) {
            o[u][0] *= a0; o[u][1] *= a0;
            o[u][2] *= a1; o[u][3] *= a1;
        }
        __syncwarp();

#pragma unroll
        for (int kc = 0; kc < 8; kc++) {
            uint32_t a[4];
            a[0] = f2tf32(QP[(wm + g8) * QPIT + kc * 8 + q]);
            a[1] = f2tf32(QP[(wm + g8 + 8) * QPIT + kc * 8 + q]);
            a[2] = f2tf32(QP[(wm + g8) * QPIT + kc * 8 + q + 4]);
            a[3] = f2tf32(QP[(wm + g8 + 8) * QPIT + kc * 8 + q + 4]);
#pragma unroll
            for (int u = 0; u < 8; u++) {
                uint32_t b[2];
                b[0] = __float_as_uint(Vst[(kc * 8 + q) * VPIT + u * 8 + g8]);
                b[1] = __float_as_uint(Vst[(kc * 8 + q + 4) * VPIT + u * 8 + g8]);
                mma_tf32(o[u], a, b);
            }
        }

        __syncthreads();   // RACE FIX: all warps done reading stage kt&1
                           // before anyone issues next cp.async into it
    }

    // ---- epilogue: normalize, write merged-head raw Y ----
    const int b = bh >> 4, h = bh & 15;
    const float i0 = 1.0f / l0;
    const float i1 = 1.0f / l1;
    float* Y0 = g_Y + ((size_t)b * S_LEN + row0) * EMB + h * DH;
    float* Y1 = g_Y + ((size_t)b * S_LEN + row1) * EMB + h * DH;
#pragma unroll
    for (int u = 0; u < 8; u++) {
        const int c = u * 8 + 2 * q;
        *(float2*)&Y0[c] = make_float2(o[u][0] * i0, o[u][1] * i0);
        *(float2*)&Y1[c] = make_float2(o[u][2] * i1, o[u][3] * i1);
    }
}

// ---------------------------------------------------------------------------
extern "C" void kernel_launch(void* const* d_in, const int* in_sizes, int n_in,
                              void* d_out, int out_size)
{
    (void)in_sizes; (void)n_in; (void)out_size;
    const float* x  = (const float*)d_in[0];
    const float* Wq = (const float*)d_in[1];
    const float* Wk = (const float*)d_in[2];
    const float* Wv = (const float*)d_in[3];
    const float* Wo = (const float*)d_in[4];
    float* out = (float*)d_out;

    static bool attr_done = false;       // idempotent setup (not a work guard)
    static float4* p_Ws = nullptr;
    if (!attr_done) {
        cudaFuncSetAttribute(gemm_hs<true>,
                             cudaFuncAttributeMaxDynamicSharedMemorySize, HGSMEM);
        cudaFuncSetAttribute(gemm_hs<false>,
                             cudaFuncAttributeMaxDynamicSharedMemorySize, HGSMEM);
        cudaFuncSetAttribute(flash_mma,
                             cudaFuncAttributeMaxDynamicSharedMemorySize, FLASH_SMEM);
        cudaGetSymbolAddress((void**)&p_Ws, g_Ws);
        attr_done = true;
    }

    // 0) pre-split weights only (~7 us total)
    split_tf32<<<1024, 256>>>((const float4*)Wq, p_Ws,            262144);
    split_tf32<<<1024, 256>>>((const float4*)Wk, p_Ws + 524288,   262144);
    split_tf32<<<1024, 256>>>((const float4*)Wv, p_Ws + 1048576,  262144);
    split_tf32<<<1024, 256>>>((const float4*)Wo, p_Ws + 1572864,  262144);
    // 1) QKV projections (hybrid 3xTF32, race-free)
    gemm_hs<true><<<dim3(64, 8, 3), 256, HGSMEM>>>(x, nullptr);
    // 2) Causal flash attention (3xTF32 QK, 1xTF32 PV, race FIXED, LPT)
    flash_mma<<<dim3(64, 16), 256, FLASH_SMEM>>>();
    // 3) Output projection
    gemm_hs<false><<<dim3(64, 8), 256, HGSMEM>>>(nullptr, out);
}

// round 13
// speedup vs baseline: 1.8035x; 1.3993x over previous
#include <cuda_runtime.h>
#include <cstdint>

#define BATCH 4
#define S_LEN 2048
#define EMB   1024
#define NH    16
#define DH    64

// Scratch (allocation-free rule: __device__ globals)
__device__ uint16_t g_Xh[8388608], g_Xl[8388608];   // X bf16 planes [8192,1024]
__device__ uint16_t g_Wh[4194304], g_Wl[4194304];   // Wq,Wk,Wv,Wo planes
__device__ float    g_Q [8388608];                  // raw fp32 [B,H,S,Dh]
__device__ float    g_K [8388608];                  // raw fp32 [B,H,S,Dh]
__device__ float    g_V [8388608];                  // tf32-rounded fp32
__device__ uint16_t g_Yh[8388608], g_Yl[8388608];   // Y bf16 planes [B,S,E]

// ===========================================================================
// Helpers
// ===========================================================================
__device__ __forceinline__ uint32_t smem_u32(const void* p) {
    uint32_t a;
    asm("{ .reg .u64 t; cvta.to.shared.u64 t, %1; cvt.u32.u64 %0, t; }"
        : "=r"(a) : "l"(p));
    return a;
}
__device__ __forceinline__ void cp_async16(uint32_t s, const void* g) {
    asm volatile("cp.async.cg.shared.global [%0], [%1], 16;" :: "r"(s), "l"(g));
}
__device__ __forceinline__ void cp_commit() {
    asm volatile("cp.async.commit_group;" ::: "memory");
}
template <int N>
__device__ __forceinline__ void cp_wait_group() {
    asm volatile("cp.async.wait_group %0;" :: "n"(N) : "memory");
}
__device__ __forceinline__ void mma_bf16(float* c, const uint32_t* a, const uint32_t* b) {
    asm volatile(
        "mma.sync.aligned.m16n8k16.row.col.f32.bf16.bf16.f32 "
        "{%0,%1,%2,%3}, {%4,%5,%6,%7}, {%8,%9}, {%0,%1,%2,%3};"
        : "+f"(c[0]), "+f"(c[1]), "+f"(c[2]), "+f"(c[3])
        : "r"(a[0]), "r"(a[1]), "r"(a[2]), "r"(a[3]), "r"(b[0]), "r"(b[1]));
}
__device__ __forceinline__ void mma_tf32(float* c, const uint32_t* a, const uint32_t* b) {
    asm volatile(
        "mma.sync.aligned.m16n8k8.row.col.f32.tf32.tf32.f32 "
        "{%0,%1,%2,%3}, {%4,%5,%6,%7}, {%8,%9}, {%0,%1,%2,%3};"
        : "+f"(c[0]), "+f"(c[1]), "+f"(c[2]), "+f"(c[3])
        : "r"(a[0]), "r"(a[1]), "r"(a[2]), "r"(a[3]), "r"(b[0]), "r"(b[1]));
}
__device__ __forceinline__ uint32_t f2tf32(float x) {
    uint32_t r;
    asm("cvt.rna.tf32.f32 %0, %1;" : "=r"(r) : "f"(x));
    return r;
}
__device__ __forceinline__ float rtf(float x) { return __uint_as_float(f2tf32(x)); }

// bf16 split via integer bit ops (RN); lo is an unfoldable exact FSUB.
__device__ __forceinline__ uint32_t bf_rn_bits(float x) {
    const uint32_t b = __float_as_uint(x);
    return (b + 0x7FFFu + ((b >> 16) & 1u)) & 0xFFFF0000u;
}
__device__ __forceinline__ void bf_split(float x, uint16_t& h, uint16_t& l) {
    const uint32_t hb = bf_rn_bits(x);
    h = (uint16_t)(hb >> 16);
    const float lo = x - __uint_as_float(hb);
    l = (uint16_t)(bf_rn_bits(lo) >> 16);
}

// ===========================================================================
// Pre-split fp32 -> bf16 hi/lo planes
// ===========================================================================
__global__ __launch_bounds__(256) void split_bf(const float4* __restrict__ src,
                                                uint16_t* __restrict__ dh,
                                                uint16_t* __restrict__ dl, int n4)
{
    const int i = blockIdx.x * 256 + threadIdx.x;
    if (i >= n4) return;
    const float4 v = src[i];
    uint16_t h0, h1, h2, h3, l0, l1, l2, l3;
    bf_split(v.x, h0, l0); bf_split(v.y, h1, l1);
    bf_split(v.z, h2, l2); bf_split(v.w, h3, l3);
    *(uint2*)(dh + 4 * (size_t)i) =
        make_uint2((uint32_t)h0 | ((uint32_t)h1 << 16), (uint32_t)h2 | ((uint32_t)h3 << 16));
    *(uint2*)(dl + 4 * (size_t)i) =
        make_uint2((uint32_t)l0 | ((uint32_t)l1 << 16), (uint32_t)l2 | ((uint32_t)l3 << 16));
}

// ===========================================================================
// 3xbf16 GEMM (race-free; own trailing barrier): C = A * W^T, hi/lo planes.
// BM=128, BN=128, BK=32; stage = 40960B, 2 stages = 81920B (2 CTAs/SM).
// Epilogue writes raw fp32 Q/K and tf32-rounded V (tf32-flash contract).
// ===========================================================================
#define GSTG   40960
#define GSMEM2 81920

template <bool SCATTER>
__global__ __launch_bounds__(256, 2) void gemm_bf(float* __restrict__ outp)
{
    const uint16_t *Aph, *Apl, *Bph, *Bpl;
    if (SCATTER) {
        Aph = g_Xh; Apl = g_Xl;
        Bph = g_Wh + (size_t)blockIdx.z * 1048576;
        Bpl = g_Wl + (size_t)blockIdx.z * 1048576;
    } else {
        Aph = g_Yh; Apl = g_Yl;
        Bph = g_Wh + 3145728; Bpl = g_Wl + 3145728;
    }

    extern __shared__ __align__(16) char smc[];
    const int tid  = threadIdx.x;
    const int wid  = tid >> 5;
    const int lane = tid & 31;
    const int m0   = blockIdx.x * 128;
    const int n0   = blockIdx.y * 128;
    const int wm   = (wid >> 1) * 32;
    const int wn   = (wid & 1) * 64;
    const int q    = lane & 3;
    const int g8   = lane >> 2;
    const uint32_t sbase = smem_u32(smc);

    auto load_stage = [&](int kt, uint32_t soff) {
#pragma unroll
        for (int j = 0; j < 4; j++) {
            const int f = tid + 256 * j;
            const int pl = f >> 9, r = (f >> 2) & 127, c = f & 3;
            const uint16_t* ap = pl ? Apl : Aph;
            cp_async16(sbase + soff + (uint32_t)(pl * 10240 + r * 80 + c * 16),
                       ap + ((size_t)(m0 + r)) * 1024 + kt * 32 + c * 8);
        }
#pragma unroll
        for (int j = 0; j < 4; j++) {
            const int f = tid + 256 * j;
            const int pl = f >> 9, r = (f >> 2) & 127, c = f & 3;
            const uint16_t* bp = pl ? Bpl : Bph;
            cp_async16(sbase + soff + (uint32_t)(20480 + pl * 10240 + r * 80 + c * 16),
                       bp + ((size_t)(n0 + r)) * 1024 + kt * 32 + c * 8);
        }
        cp_commit();
    };

    load_stage(0, 0);

    float acc[2][8][4];
#pragma unroll
    for (int t = 0; t < 2; t++)
#pragma unroll
        for (int u = 0; u < 8; u++)
#pragma unroll
            for (int r = 0; r < 4; r++) acc[t][u][r] = 0.f;

    for (int kt = 0; kt < 32; kt++) {
        if (kt + 1 < 32) {
            load_stage(kt + 1, ((kt + 1) & 1) * (uint32_t)GSTG);
            cp_wait_group<1>();
        } else {
            cp_wait_group<0>();
        }
        __syncthreads();

        const char* stg = smc + (kt & 1) * GSTG;
        const char* Ah = stg;
        const char* Al = stg + 10240;
        const char* Bh = stg + 20480;
        const char* Bl = stg + 30720;

#pragma unroll
        for (int ks = 0; ks < 2; ks++) {
            const int kb = ks * 32 + 4 * q;
            uint32_t ah[2][4], al[2][4];
#pragma unroll
            for (int t = 0; t < 2; t++) {
                const int r0 = (wm + t * 16 + g8) * 80;
                ah[t][0] = *(const uint32_t*)(Ah + r0 + kb);
                ah[t][1] = *(const uint32_t*)(Ah + r0 + 640 + kb);
                ah[t][2] = *(const uint32_t*)(Ah + r0 + kb + 16);
                ah[t][3] = *(const uint32_t*)(Ah + r0 + 640 + kb + 16);
                al[t][0] = *(const uint32_t*)(Al + r0 + kb);
                al[t][1] = *(const uint32_t*)(Al + r0 + 640 + kb);
                al[t][2] = *(const uint32_t*)(Al + r0 + kb + 16);
                al[t][3] = *(const uint32_t*)(Al + r0 + 640 + kb + 16);
            }
#pragma unroll
            for (int u = 0; u < 8; u++) {
                const int nb = (wn + u * 8 + g8) * 80 + kb;
                uint32_t bh[2], bl[2];
                bh[0] = *(const uint32_t*)(Bh + nb);
                bh[1] = *(const uint32_t*)(Bh + nb + 16);
                bl[0] = *(const uint32_t*)(Bl + nb);
                bl[1] = *(const uint32_t*)(Bl + nb + 16);
#pragma unroll
                for (int t = 0; t < 2; t++) {
                    mma_bf16(acc[t][u], ah[t], bh);
                    mma_bf16(acc[t][u], ah[t], bl);
                    mma_bf16(acc[t][u], al[t], bh);
                }
            }
        }
        __syncthreads();    // all reads done before next stage overwrite
    }

    // ---- epilogue ----
    const int z = SCATTER ? blockIdx.z : 3;
#pragma unroll
    for (int t = 0; t < 2; t++) {
#pragma unroll
        for (int u = 0; u < 8; u++) {
            const int m = m0 + wm + t * 16 + g8;
            const int n = n0 + wn + u * 8 + q * 2;
#pragma unroll
            for (int hh = 0; hh < 2; hh++) {
                const int mm = m + hh * 8;
                const float v0 = acc[t][u][hh * 2];
                const float v1 = acc[t][u][hh * 2 + 1];
                if (SCATTER) {
                    const int bb = mm >> 11, s = mm & 2047;
                    const int h = n >> 6, d0 = n & 63;
                    const size_t e = (((size_t)bb * NH + h) * S_LEN + s) * DH + d0;
                    if (z == 0)      *(float2*)(g_Q + e) = make_float2(v0, v1);
                    else if (z == 1) *(float2*)(g_K + e) = make_float2(v0, v1);
                    else             *(float2*)(g_V + e) = make_float2(rtf(v0), rtf(v1));
                } else {
                    *(float2*)(outp + (size_t)mm * EMB + n) = make_float2(v0, v1);
                }
            }
        }
    }
}

// ===========================================================================
// Flash attention — round-12 PROVEN kernel (3xTF32 QK, 1xTF32 PV, race-fixed,
// LPT, scale-fold). ONLY change: epilogue writes Y as bf16 planes.
// ===========================================================================
#define QPIT 68
#define KPIT 68
#define VPIT 72
#define QP_F   (128 * QPIT)
#define KST_F  (64 * KPIT)
#define VST_F  (64 * VPIT)
#define FLASH_SMEM ((QP_F + 2 * KST_F + 2 * VST_F) * 4)   // 106496 B

__global__ __launch_bounds__(256) void flash_mma()
{
    const int bh = blockIdx.x;
    const int qi = 15 - blockIdx.y;          // LPT: long jobs first

    extern __shared__ __align__(16) float sm[];
    float* QP = sm;
    float* Kb = sm + QP_F;
    float* Vb = Kb + 2 * KST_F;

    const int tid  = threadIdx.x;
    const int wid  = tid >> 5;
    const int lane = tid & 31;
    const int g8   = lane >> 2;
    const int q    = lane & 3;
    const int wm   = wid * 16;

    const float* Qg = g_Q + ((size_t)bh * S_LEN + (size_t)qi * 128) * DH;
    const float* Kg = g_K + (size_t)bh * S_LEN * DH;
    const float* Vg = g_V + (size_t)bh * S_LEN * DH;

    const uint32_t sbase = smem_u32(sm);
    const uint32_t kboff = (uint32_t)(QP_F * 4);
    const uint32_t vboff = (uint32_t)((QP_F + 2 * KST_F) * 4);

#pragma unroll
    for (int j = 0; j < 8; j++) {
        const int f = tid + 256 * j, row = f >> 4, c4 = f & 15;
        cp_async16(sbase + (uint32_t)((row * QPIT + c4 * 4) * 4),
                   Qg + row * DH + c4 * 4);
    }
    cp_commit();
#pragma unroll
    for (int j = 0; j < 4; j++) {
        const int f = tid + 256 * j, row = f >> 4, c4 = f & 15;
        cp_async16(sbase + kboff + (uint32_t)((row * KPIT + c4 * 4) * 4),
                   Kg + row * DH + c4 * 4);
        cp_async16(sbase + vboff + (uint32_t)((row * VPIT + c4 * 4) * 4),
                   Vg + row * DH + c4 * 4);
    }
    cp_commit();

    cp_wait_group<1>();
    __syncthreads();

    // ---- hoist Q fragments (3xTF32 split; 1/8 scale folded in, exact) ----
    uint32_t qh[8][4], ql[8][4];
#pragma unroll
    for (int kc = 0; kc < 8; kc++) {
        const float f0 = 0.125f * QP[(wm + g8) * QPIT + kc * 8 + q];
        const float f1 = 0.125f * QP[(wm + g8 + 8) * QPIT + kc * 8 + q];
        const float f2 = 0.125f * QP[(wm + g8) * QPIT + kc * 8 + q + 4];
        const float f3 = 0.125f * QP[(wm + g8 + 8) * QPIT + kc * 8 + q + 4];
        qh[kc][0] = f2tf32(f0); ql[kc][0] = f2tf32(f0 - __uint_as_float(qh[kc][0]));
        qh[kc][1] = f2tf32(f1); ql[kc][1] = f2tf32(f1 - __uint_as_float(qh[kc][1]));
        qh[kc][2] = f2tf32(f2); ql[kc][2] = f2tf32(f2 - __uint_as_float(qh[kc][2]));
        qh[kc][3] = f2tf32(f3); ql[kc][3] = f2tf32(f3 - __uint_as_float(qh[kc][3]));
    }
    __syncthreads();

    float m0 = -1e30f, m1 = -1e30f, l0 = 0.f, l1 = 0.f;
    float o[8][4];
#pragma unroll
    for (int u = 0; u < 8; u++)
#pragma unroll
        for (int r = 0; r < 4; r++) o[u][r] = 0.f;

    const int row0 = qi * 128 + wm + g8;
    const int row1 = row0 + 8;
    const int last = 2 * qi + 1;

    for (int kt = 0; kt <= last; kt++) {
        if (kt < last) {
            const int st = (kt + 1) & 1;
            const float* kp = Kg + (size_t)(kt + 1) * 64 * DH;
            const float* vp = Vg + (size_t)(kt + 1) * 64 * DH;
#pragma unroll
            for (int j = 0; j < 4; j++) {
                const int f = tid + 256 * j, row = f >> 4, c4 = f & 15;
                cp_async16(sbase + kboff + (uint32_t)((st * KST_F + row * KPIT + c4 * 4) * 4),
                           kp + row * DH + c4 * 4);
                cp_async16(sbase + vboff + (uint32_t)((st * VST_F + row * VPIT + c4 * 4) * 4),
                           vp + row * DH + c4 * 4);
            }
            cp_commit();
            cp_wait_group<1>();
        } else {
            cp_wait_group<0>();
        }
        __syncthreads();

        const float* Kst = Kb + (kt & 1) * KST_F;
        const float* Vst = Vb + (kt & 1) * VST_F;

        float s[8][4];
#pragma unroll
        for (int u = 0; u < 8; u++)
#pragma unroll
            for (int r = 0; r < 4; r++) s[u][r] = 0.f;

#pragma unroll
        for (int kc = 0; kc < 8; kc++) {
#pragma unroll
            for (int u = 0; u < 8; u++) {
                const float bf0 = Kst[(u * 8 + g8) * KPIT + kc * 8 + q];
                const float bf1 = Kst[(u * 8 + g8) * KPIT + kc * 8 + q + 4];
                uint32_t bh[2], bl[2];
                bh[0] = f2tf32(bf0);
                bh[1] = f2tf32(bf1);
                bl[0] = f2tf32(bf0 - __uint_as_float(bh[0]));
                bl[1] = f2tf32(bf1 - __uint_as_float(bh[1]));
                mma_tf32(s[u], qh[kc], bh);
                mma_tf32(s[u], qh[kc], bl);
                mma_tf32(s[u], ql[kc], bh);
            }
        }

        if (kt >= 2 * qi) {
            const int cb = kt * 64;
#pragma unroll
            for (int u = 0; u < 8; u++) {
                const int c = cb + u * 8 + 2 * q;
                if (c     > row0) s[u][0] = -1e30f;
                if (c + 1 > row0) s[u][1] = -1e30f;
                if (c     > row1) s[u][2] = -1e30f;
                if (c + 1 > row1) s[u][3] = -1e30f;
            }
        }

        float tm0 = -1e30f, tm1 = -1e30f;
#pragma unroll
        for (int u = 0; u < 8; u++) {
            tm0 = fmaxf(tm0, fmaxf(s[u][0], s[u][1]));
            tm1 = fmaxf(tm1, fmaxf(s[u][2], s[u][3]));
        }
        tm0 = fmaxf(tm0, __shfl_xor_sync(0xffffffffu, tm0, 1));
        tm0 = fmaxf(tm0, __shfl_xor_sync(0xffffffffu, tm0, 2));
        tm1 = fmaxf(tm1, __shfl_xor_sync(0xffffffffu, tm1, 1));
        tm1 = fmaxf(tm1, __shfl_xor_sync(0xffffffffu, tm1, 2));

        const float mn0 = fmaxf(m0, tm0);
        const float mn1 = fmaxf(m1, tm1);
        const float a0 = __expf(m0 - mn0);
        const float a1 = __expf(m1 - mn1);

        float ps0 = 0.f, ps1 = 0.f;
#pragma unroll
        for (int u = 0; u < 8; u++) {
            const float p00 = __expf(s[u][0] - mn0);
            const float p01 = __expf(s[u][1] - mn0);
            const float p10 = __expf(s[u][2] - mn1);
            const float p11 = __expf(s[u][3] - mn1);
            ps0 += p00 + p01;
            ps1 += p10 + p11;
            *(float2*)&QP[(wm + g8) * QPIT + u * 8 + 2 * q]     = make_float2(p00, p01);
            *(float2*)&QP[(wm + g8 + 8) * QPIT + u * 8 + 2 * q] = make_float2(p10, p11);
        }
        ps0 += __shfl_xor_sync(0xffffffffu, ps0, 1);
        ps0 += __shfl_xor_sync(0xffffffffu, ps0, 2);
        ps1 += __shfl_xor_sync(0xffffffffu, ps1, 1);
        ps1 += __shfl_xor_sync(0xffffffffu, ps1, 2);

        l0 = l0 * a0 + ps0;
        l1 = l1 * a1 + ps1;
        m0 = mn0;
        m1 = mn1;
#pragma unroll
        for (int u = 0; u < 8; u++) {
            o[u][0] *= a0; o[u][1] *= a0;
            o[u][2] *= a1; o[u][3] *= a1;
        }
        __syncwarp();

#pragma unroll
        for (int kc = 0; kc < 8; kc++) {
            uint32_t a[4];
            a[0] = f2tf32(QP[(wm + g8) * QPIT + kc * 8 + q]);
            a[1] = f2tf32(QP[(wm + g8 + 8) * QPIT + kc * 8 + q]);
            a[2] = f2tf32(QP[(wm + g8) * QPIT + kc * 8 + q + 4]);
            a[3] = f2tf32(QP[(wm + g8 + 8) * QPIT + kc * 8 + q + 4]);
#pragma unroll
            for (int u = 0; u < 8; u++) {
                uint32_t b[2];
                b[0] = __float_as_uint(Vst[(kc * 8 + q) * VPIT + u * 8 + g8]);
                b[1] = __float_as_uint(Vst[(kc * 8 + q + 4) * VPIT + u * 8 + g8]);
                mma_tf32(o[u], a, b);
            }
        }

        __syncthreads();   // RACE FIX: all warps done reading stage kt&1
                           // before anyone issues next cp.async into it
    }

    // ---- epilogue: normalize, write Y as bf16 planes for the out-proj ----
    const int b = bh >> 4, h = bh & 15;
    const float i0 = 1.0f / l0;
    const float i1 = 1.0f / l1;
#pragma unroll
    for (int u = 0; u < 8; u++) {
        const int c = u * 8 + 2 * q;
        const size_t e0 = ((size_t)b * S_LEN + row0) * EMB + h * 64 + c;
        const size_t e1 = ((size_t)b * S_LEN + row1) * EMB + h * 64 + c;
        const float y0 = o[u][0] * i0, y1 = o[u][1] * i0;
        const float y2 = o[u][2] * i1, y3 = o[u][3] * i1;
        uint16_t h0, lo0, h1, lo1, h2, lo2, h3, lo3;
        bf_split(y0, h0, lo0); bf_split(y1, h1, lo1);
        bf_split(y2, h2, lo2); bf_split(y3, h3, lo3);
        *(uint32_t*)&g_Yh[e0] = (uint32_t)h0 | ((uint32_t)h1 << 16);
        *(uint32_t*)&g_Yl[e0] = (uint32_t)lo0 | ((uint32_t)lo1 << 16);
        *(uint32_t*)&g_Yh[e1] = (uint32_t)h2 | ((uint32_t)h3 << 16);
        *(uint32_t*)&g_Yl[e1] = (uint32_t)lo2 | ((uint32_t)lo3 << 16);
    }
}

// ---------------------------------------------------------------------------
extern "C" void kernel_launch(void* const* d_in, const int* in_sizes, int n_in,
                              void* d_out, int out_size)
{
    (void)in_sizes; (void)n_in; (void)out_size;
    const float* x  = (const float*)d_in[0];
    const float* Wq = (const float*)d_in[1];
    const float* Wk = (const float*)d_in[2];
    const float* Wv = (const float*)d_in[3];
    const float* Wo = (const float*)d_in[4];
    float* out = (float*)d_out;

    static bool attr_done = false;       // idempotent setup (not a work guard)
    static uint16_t *pXh, *pXl, *pWh, *pWl;
    if (!attr_done) {
        cudaFuncSetAttribute(gemm_bf<true>,
                             cudaFuncAttributeMaxDynamicSharedMemorySize, GSMEM2);
        cudaFuncSetAttribute(gemm_bf<false>,
                             cudaFuncAttributeMaxDynamicSharedMemorySize, GSMEM2);
        cudaFuncSetAttribute(flash_mma,
                             cudaFuncAttributeMaxDynamicSharedMemorySize, FLASH_SMEM);
        cudaGetSymbolAddress((void**)&pXh, g_Xh);
        cudaGetSymbolAddress((void**)&pXl, g_Xl);
        cudaGetSymbolAddress((void**)&pWh, g_Wh);
        cudaGetSymbolAddress((void**)&pWl, g_Wl);
        attr_done = true;
    }

    // 0) split X and weights into bf16 hi/lo planes
    split_bf<<<8192, 256>>>((const float4*)x,  pXh, pXl, 2097152);
    split_bf<<<1024, 256>>>((const float4*)Wq, pWh,           pWl,           262144);
    split_bf<<<1024, 256>>>((const float4*)Wk, pWh + 1048576, pWl + 1048576, 262144);
    split_bf<<<1024, 256>>>((const float4*)Wv, pWh + 2097152, pWl + 2097152, 262144);
    split_bf<<<1024, 256>>>((const float4*)Wo, pWh + 3145728, pWl + 3145728, 262144);
    // 1) QKV projections (3xbf16 — half the HMMA count, race-free)
    gemm_bf<true><<<dim3(64, 8, 3), 256, GSMEM2>>>(nullptr);
    // 2) Causal flash attention (round-12 PROVEN, race-fixed; bf16-plane Y out)
    flash_mma<<<dim3(64, 16), 256, FLASH_SMEM>>>();
    // 3) Output projection (3xbf16)
    gemm_bf<false><<<dim3(64, 8), 256, GSMEM2>>>(out);
}

// round 14
// speedup vs baseline: 2.1827x; 1.2103x over previous
#include <cuda_runtime.h>
#include <cstdint>

#define BATCH 4
#define S_LEN 2048
#define EMB   1024
#define NH    16
#define DH    64

// Scratch (allocation-free rule: __device__ globals). bf16 hi/lo planes.
__device__ uint16_t g_Xh[8388608], g_Xl[8388608];   // X  [8192,1024]
__device__ uint16_t g_Wh[4194304], g_Wl[4194304];   // Wq,Wk,Wv,Wo
__device__ uint16_t g_Qh[8388608], g_Ql[8388608];   // Q  [B,H,S,Dh] (x0.125 folded)
__device__ uint16_t g_Kh[8388608], g_Kl[8388608];   // K  [B,H,S,Dh]
__device__ float    g_V [8388608];                  // V  tf32-rounded fp32
__device__ uint16_t g_Yh[8388608], g_Yl[8388608];   // Y  [B,S,E]

// ===========================================================================
// Helpers
// ===========================================================================
__device__ __forceinline__ uint32_t smem_u32(const void* p) {
    uint32_t a;
    asm("{ .reg .u64 t; cvta.to.shared.u64 t, %1; cvt.u32.u64 %0, t; }"
        : "=r"(a) : "l"(p));
    return a;
}
__device__ __forceinline__ void cp_async16(uint32_t s, const void* g) {
    asm volatile("cp.async.cg.shared.global [%0], [%1], 16;" :: "r"(s), "l"(g));
}
__device__ __forceinline__ void cp_commit() {
    asm volatile("cp.async.commit_group;" ::: "memory");
}
template <int N>
__device__ __forceinline__ void cp_wait_group() {
    asm volatile("cp.async.wait_group %0;" :: "n"(N) : "memory");
}
__device__ __forceinline__ void mma_bf16(float* c, const uint32_t* a, const uint32_t* b) {
    asm volatile(
        "mma.sync.aligned.m16n8k16.row.col.f32.bf16.bf16.f32 "
        "{%0,%1,%2,%3}, {%4,%5,%6,%7}, {%8,%9}, {%0,%1,%2,%3};"
        : "+f"(c[0]), "+f"(c[1]), "+f"(c[2]), "+f"(c[3])
        : "r"(a[0]), "r"(a[1]), "r"(a[2]), "r"(a[3]), "r"(b[0]), "r"(b[1]));
}
__device__ __forceinline__ void mma_tf32(float* c, const uint32_t* a, const uint32_t* b) {
    asm volatile(
        "mma.sync.aligned.m16n8k8.row.col.f32.tf32.tf32.f32 "
        "{%0,%1,%2,%3}, {%4,%5,%6,%7}, {%8,%9}, {%0,%1,%2,%3};"
        : "+f"(c[0]), "+f"(c[1]), "+f"(c[2]), "+f"(c[3])
        : "r"(a[0]), "r"(a[1]), "r"(a[2]), "r"(a[3]), "r"(b[0]), "r"(b[1]));
}
__device__ __forceinline__ uint32_t f2tf32(float x) {
    uint32_t r;
    asm("cvt.rna.tf32.f32 %0, %1;" : "=r"(r) : "f"(x));
    return r;
}
__device__ __forceinline__ float rtf(float x) { return __uint_as_float(f2tf32(x)); }

// bf16 split via integer bit ops (RN); lo is an unfoldable exact FSUB.
__device__ __forceinline__ uint32_t bf_rn_bits(float x) {
    const uint32_t b = __float_as_uint(x);
    return (b + 0x7FFFu + ((b >> 16) & 1u)) & 0xFFFF0000u;
}
__device__ __forceinline__ void bf_split(float x, uint16_t& h, uint16_t& l) {
    const uint32_t hb = bf_rn_bits(x);
    h = (uint16_t)(hb >> 16);
    const float lo = x - __uint_as_float(hb);
    l = (uint16_t)(bf_rn_bits(lo) >> 16);
}

// ===========================================================================
// Pre-split fp32 -> bf16 hi/lo planes
// ===========================================================================
__global__ __launch_bounds__(256) void split_bf(const float4* __restrict__ src,
                                                uint16_t* __restrict__ dh,
                                                uint16_t* __restrict__ dl, int n4)
{
    const int i = blockIdx.x * 256 + threadIdx.x;
    if (i >= n4) return;
    const float4 v = src[i];
    uint16_t h0, h1, h2, h3, l0, l1, l2, l3;
    bf_split(v.x, h0, l0); bf_split(v.y, h1, l1);
    bf_split(v.z, h2, l2); bf_split(v.w, h3, l3);
    *(uint2*)(dh + 4 * (size_t)i) =
        make_uint2((uint32_t)h0 | ((uint32_t)h1 << 16), (uint32_t)h2 | ((uint32_t)h3 << 16));
    *(uint2*)(dl + 4 * (size_t)i) =
        make_uint2((uint32_t)l0 | ((uint32_t)l1 << 16), (uint32_t)l2 | ((uint32_t)l3 << 16));
}

// ===========================================================================
// 3xbf16 GEMM (race-free, proven round 13): C = A * W^T, hi/lo planes.
// Epilogue: Q bf16 planes (x0.125 folded), K bf16 planes, V tf32-rounded.
// ===========================================================================
#define GSTG   40960
#define GSMEM2 81920

template <bool SCATTER>
__global__ __launch_bounds__(256, 2) void gemm_bf(float* __restrict__ outp)
{
    const uint16_t *Aph, *Apl, *Bph, *Bpl;
    if (SCATTER) {
        Aph = g_Xh; Apl = g_Xl;
        Bph = g_Wh + (size_t)blockIdx.z * 1048576;
        Bpl = g_Wl + (size_t)blockIdx.z * 1048576;
    } else {
        Aph = g_Yh; Apl = g_Yl;
        Bph = g_Wh + 3145728; Bpl = g_Wl + 3145728;
    }

    extern __shared__ __align__(16) char smc[];
    const int tid  = threadIdx.x;
    const int wid  = tid >> 5;
    const int lane = tid & 31;
    const int m0   = blockIdx.x * 128;
    const int n0   = blockIdx.y * 128;
    const int wm   = (wid >> 1) * 32;
    const int wn   = (wid & 1) * 64;
    const int q    = lane & 3;
    const int g8   = lane >> 2;
    const uint32_t sbase = smem_u32(smc);

    auto load_stage = [&](int kt, uint32_t soff) {
#pragma unroll
        for (int j = 0; j < 4; j++) {
            const int f = tid + 256 * j;
            const int pl = f >> 9, r = (f >> 2) & 127, c = f & 3;
            const uint16_t* ap = pl ? Apl : Aph;
            cp_async16(sbase + soff + (uint32_t)(pl * 10240 + r * 80 + c * 16),
                       ap + ((size_t)(m0 + r)) * 1024 + kt * 32 + c * 8);
        }
#pragma unroll
        for (int j = 0; j < 4; j++) {
            const int f = tid + 256 * j;
            const int pl = f >> 9, r = (f >> 2) & 127, c = f & 3;
            const uint16_t* bp = pl ? Bpl : Bph;
            cp_async16(sbase + soff + (uint32_t)(20480 + pl * 10240 + r * 80 + c * 16),
                       bp + ((size_t)(n0 + r)) * 1024 + kt * 32 + c * 8);
        }
        cp_commit();
    };

    load_stage(0, 0);

    float acc[2][8][4];
#pragma unroll
    for (int t = 0; t < 2; t++)
#pragma unroll
        for (int u = 0; u < 8; u++)
#pragma unroll
            for (int r = 0; r < 4; r++) acc[t][u][r] = 0.f;

    for (int kt = 0; kt < 32; kt++) {
        if (kt + 1 < 32) {
            load_stage(kt + 1, ((kt + 1) & 1) * (uint32_t)GSTG);
            cp_wait_group<1>();
        } else {
            cp_wait_group<0>();
        }
        __syncthreads();

        const char* stg = smc + (kt & 1) * GSTG;
        const char* Ah = stg;
        const char* Al = stg + 10240;
        const char* Bh = stg + 20480;
        const char* Bl = stg + 30720;

#pragma unroll
        for (int ks = 0; ks < 2; ks++) {
            const int kb = ks * 32 + 4 * q;
            uint32_t ah[2][4], al[2][4];
#pragma unroll
            for (int t = 0; t < 2; t++) {
                const int r0 = (wm + t * 16 + g8) * 80;
                ah[t][0] = *(const uint32_t*)(Ah + r0 + kb);
                ah[t][1] = *(const uint32_t*)(Ah + r0 + 640 + kb);
                ah[t][2] = *(const uint32_t*)(Ah + r0 + kb + 16);
                ah[t][3] = *(const uint32_t*)(Ah + r0 + 640 + kb + 16);
                al[t][0] = *(const uint32_t*)(Al + r0 + kb);
                al[t][1] = *(const uint32_t*)(Al + r0 + 640 + kb);
                al[t][2] = *(const uint32_t*)(Al + r0 + kb + 16);
                al[t][3] = *(const uint32_t*)(Al + r0 + 640 + kb + 16);
            }
#pragma unroll
            for (int u = 0; u < 8; u++) {
                const int nb = (wn + u * 8 + g8) * 80 + kb;
                uint32_t bh[2], bl[2];
                bh[0] = *(const uint32_t*)(Bh + nb);
                bh[1] = *(const uint32_t*)(Bh + nb + 16);
                bl[0] = *(const uint32_t*)(Bl + nb);
                bl[1] = *(const uint32_t*)(Bl + nb + 16);
#pragma unroll
                for (int t = 0; t < 2; t++) {
                    mma_bf16(acc[t][u], ah[t], bh);
                    mma_bf16(acc[t][u], ah[t], bl);
                    mma_bf16(acc[t][u], al[t], bh);
                }
            }
        }
        __syncthreads();    // all reads done before next stage overwrite
    }

    // ---- epilogue ----
    const int z = SCATTER ? blockIdx.z : 3;
#pragma unroll
    for (int t = 0; t < 2; t++) {
#pragma unroll
        for (int u = 0; u < 8; u++) {
            const int m = m0 + wm + t * 16 + g8;
            const int n = n0 + wn + u * 8 + q * 2;
#pragma unroll
            for (int hh = 0; hh < 2; hh++) {
                const int mm = m + hh * 8;
                const float v0 = acc[t][u][hh * 2];
                const float v1 = acc[t][u][hh * 2 + 1];
                if (SCATTER) {
                    const int bb = mm >> 11, s = mm & 2047;
                    const int h = n >> 6, d0 = n & 63;
                    const size_t e = (((size_t)bb * NH + h) * S_LEN + s) * DH + d0;
                    if (z == 0) {
                        const float y0 = v0 * 0.125f, y1 = v1 * 0.125f; // exact scale fold
                        uint16_t h0, l0, h1, l1;
                        bf_split(y0, h0, l0); bf_split(y1, h1, l1);
                        *(uint32_t*)&g_Qh[e] = (uint32_t)h0 | ((uint32_t)h1 << 16);
                        *(uint32_t*)&g_Ql[e] = (uint32_t)l0 | ((uint32_t)l1 << 16);
                    } else if (z == 1) {
                        uint16_t h0, l0, h1, l1;
                        bf_split(v0, h0, l0); bf_split(v1, h1, l1);
                        *(uint32_t*)&g_Kh[e] = (uint32_t)h0 | ((uint32_t)h1 << 16);
                        *(uint32_t*)&g_Kl[e] = (uint32_t)l0 | ((uint32_t)l1 << 16);
                    } else {
                        *(float2*)(g_V + e) = make_float2(rtf(v0), rtf(v1));
                    }
                } else {
                    *(float2*)(outp + (size_t)mm * EMB + n) = make_float2(v0, v1);
                }
            }
        }
    }
}

// ===========================================================================
// Flash attention, causal. 128 q-rows/CTA, 64-key tiles.
// QK^T: 3xbf16 (Q/K hi-lo planes, scale pre-folded); PV: 1xTF32.
// RACE-FIXED (trailing barrier), LPT order. SMEM 110592 B, 2 CTAs/SM.
// Layout: Q planes 2x18432 (P fp32 pitch-68 overlays) | K planes 2x18432 | V 2x18432
// ===========================================================================
#define FLASH_SMEM 110592

__global__ __launch_bounds__(256) void flash_mma()
{
    const int bh = blockIdx.x;
    const int qi = 15 - blockIdx.y;          // LPT: long jobs first

    extern __shared__ __align__(16) char smc[];
    float* P = (float*)smc;                   // pitch 68 floats, overlays Q planes

    const int tid  = threadIdx.x;
    const int wid  = tid >> 5;
    const int lane = tid & 31;
    const int g8   = lane >> 2;
    const int q    = lane & 3;
    const int wm   = wid * 16;
    const uint32_t sbase = smem_u32(smc);

    // ---- Q planes (group 0) ----
#pragma unroll
    for (int j = 0; j < 8; j++) {
        const int f = tid + 256 * j;
        const int pl = f >> 10, ff = f & 1023, row = ff >> 3, c = ff & 7;
        const uint16_t* qp = pl ? g_Ql : g_Qh;
        cp_async16(sbase + (uint32_t)(pl * 18432 + row * 144 + c * 16),
                   qp + ((size_t)bh * S_LEN + qi * 128 + row) * 64 + c * 8);
    }
    cp_commit();
    // ---- K planes + V, stage 0 (group 1) ----
#pragma unroll
    for (int j = 0; j < 4; j++) {
        const int f = tid + 256 * j;
        const int pl = f >> 9, ff = f & 511, row = ff >> 3, c = ff & 7;
        const uint16_t* kp = pl ? g_Kl : g_Kh;
        cp_async16(sbase + (uint32_t)(36864 + pl * 9216 + row * 144 + c * 16),
                   kp + ((size_t)bh * S_LEN + row) * 64 + c * 8);
    }
#pragma unroll
    for (int j = 0; j < 4; j++) {
        const int f = tid + 256 * j;
        const int row = f >> 4, c = f & 15;
        cp_async16(sbase + (uint32_t)(73728 + row * 288 + c * 16),
                   g_V + ((size_t)bh * S_LEN + row) * 64 + c * 4);
    }
    cp_commit();

    cp_wait_group<1>();
    __syncthreads();

    // ---- hoist Q fragments (packed bf16, both planes) ----
    uint32_t qh[4][4], ql[4][4];
    {
        const char* Qhp = smc;
        const char* Qlp = smc + 18432;
        const int rb = (wm + g8) * 144;
#pragma unroll
        for (int kc = 0; kc < 4; kc++) {
            const int kb = kc * 32 + 4 * q;
            qh[kc][0] = *(const uint32_t*)(Qhp + rb + kb);
            qh[kc][1] = *(const uint32_t*)(Qhp + rb + 1152 + kb);
            qh[kc][2] = *(const uint32_t*)(Qhp + rb + kb + 16);
            qh[kc][3] = *(const uint32_t*)(Qhp + rb + 1152 + kb + 16);
            ql[kc][0] = *(const uint32_t*)(Qlp + rb + kb);
            ql[kc][1] = *(const uint32_t*)(Qlp + rb + 1152 + kb);
            ql[kc][2] = *(const uint32_t*)(Qlp + rb + kb + 16);
            ql[kc][3] = *(const uint32_t*)(Qlp + rb + 1152 + kb + 16);
        }
    }
    __syncthreads();                          // Q reads done before P stores

    float m0 = -1e30f, m1 = -1e30f, l0 = 0.f, l1 = 0.f;
    float o[8][4];
#pragma unroll
    for (int u = 0; u < 8; u++)
#pragma unroll
        for (int r = 0; r < 4; r++) o[u][r] = 0.f;

    const int row0 = qi * 128 + wm + g8;
    const int row1 = row0 + 8;
    const int last = 2 * qi + 1;

    for (int kt = 0; kt <= last; kt++) {
        if (kt < last) {
            const int st = (kt + 1) & 1;
            const size_t kbase = (size_t)bh * S_LEN + (size_t)(kt + 1) * 64;
#pragma unroll
            for (int j = 0; j < 4; j++) {
                const int f = tid + 256 * j;
                const int pl = f >> 9, ff = f & 511, row = ff >> 3, c = ff & 7;
                const uint16_t* kp = pl ? g_Kl : g_Kh;
                cp_async16(sbase + (uint32_t)(36864 + st * 18432 + pl * 9216 + row * 144 + c * 16),
                           kp + (kbase + row) * 64 + c * 8);
            }
#pragma unroll
            for (int j = 0; j < 4; j++) {
                const int f = tid + 256 * j;
                const int row = f >> 4, c = f & 15;
                cp_async16(sbase + (uint32_t)(73728 + st * 18432 + row * 288 + c * 16),
                           g_V + (kbase + row) * 64 + c * 4);
            }
            cp_commit();
            cp_wait_group<1>();
        } else {
            cp_wait_group<0>();
        }
        __syncthreads();

        const char* Khp = smc + 36864 + (kt & 1) * 18432;
        const char* Klp = Khp + 9216;
        const float* Vst = (const float*)(smc + 73728 + (kt & 1) * 18432);

        // ---- S = Q K^T (3xbf16, scale pre-folded, ALU-free) ----
        float s[8][4];
#pragma unroll
        for (int u = 0; u < 8; u++)
#pragma unroll
            for (int r = 0; r < 4; r++) s[u][r] = 0.f;

#pragma unroll
        for (int kc = 0; kc < 4; kc++) {
#pragma unroll
            for (int u = 0; u < 8; u++) {
                const int nb = (u * 8 + g8) * 144 + kc * 32 + 4 * q;
                uint32_t bh2[2], bl2[2];
                bh2[0] = *(const uint32_t*)(Khp + nb);
                bh2[1] = *(const uint32_t*)(Khp + nb + 16);
                bl2[0] = *(const uint32_t*)(Klp + nb);
                bl2[1] = *(const uint32_t*)(Klp + nb + 16);
                mma_bf16(s[u], qh[kc], bh2);
                mma_bf16(s[u], qh[kc], bl2);
                mma_bf16(s[u], ql[kc], bh2);
            }
        }

        // causal mask (diagonal tiles only)
        if (kt >= 2 * qi) {
            const int cb = kt * 64;
#pragma unroll
            for (int u = 0; u < 8; u++) {
                const int c = cb + u * 8 + 2 * q;
                if (c     > row0) s[u][0] = -1e30f;
                if (c + 1 > row0) s[u][1] = -1e30f;
                if (c     > row1) s[u][2] = -1e30f;
                if (c + 1 > row1) s[u][3] = -1e30f;
            }
        }

        // ---- online softmax (quad reduction) ----
        float tm0 = -1e30f, tm1 = -1e30f;
#pragma unroll
        for (int u = 0; u < 8; u++) {
            tm0 = fmaxf(tm0, fmaxf(s[u][0], s[u][1]));
            tm1 = fmaxf(tm1, fmaxf(s[u][2], s[u][3]));
        }
        tm0 = fmaxf(tm0, __shfl_xor_sync(0xffffffffu, tm0, 1));
        tm0 = fmaxf(tm0, __shfl_xor_sync(0xffffffffu, tm0, 2));
        tm1 = fmaxf(tm1, __shfl_xor_sync(0xffffffffu, tm1, 1));
        tm1 = fmaxf(tm1, __shfl_xor_sync(0xffffffffu, tm1, 2));

        const float mn0 = fmaxf(m0, tm0);
        const float mn1 = fmaxf(m1, tm1);
        const float a0 = __expf(m0 - mn0);
        const float a1 = __expf(m1 - mn1);

        float ps0 = 0.f, ps1 = 0.f;
#pragma unroll
        for (int u = 0; u < 8; u++) {
            const float p00 = __expf(s[u][0] - mn0);
            const float p01 = __expf(s[u][1] - mn0);
            const float p10 = __expf(s[u][2] - mn1);
            const float p11 = __expf(s[u][3] - mn1);
            ps0 += p00 + p01;
            ps1 += p10 + p11;
            *(float2*)&P[(wm + g8) * 68 + u * 8 + 2 * q]     = make_float2(p00, p01);
            *(float2*)&P[(wm + g8 + 8) * 68 + u * 8 + 2 * q] = make_float2(p10, p11);
        }
        ps0 += __shfl_xor_sync(0xffffffffu, ps0, 1);
        ps0 += __shfl_xor_sync(0xffffffffu, ps0, 2);
        ps1 += __shfl_xor_sync(0xffffffffu, ps1, 1);
        ps1 += __shfl_xor_sync(0xffffffffu, ps1, 2);

        l0 = l0 * a0 + ps0;
        l1 = l1 * a1 + ps1;
        m0 = mn0;
        m1 = mn1;
#pragma unroll
        for (int u = 0; u < 8; u++) {
            o[u][0] *= a0; o[u][1] *= a0;
            o[u][2] *= a1; o[u][3] *= a1;
        }
        __syncwarp();   // P visible within warp

        // ---- O += P @ V (1xTF32; V pre-rounded) ----
#pragma unroll
        for (int kc = 0; kc < 8; kc++) {
            uint32_t a[4];
            a[0] = f2tf32(P[(wm + g8) * 68 + kc * 8 + q]);
            a[1] = f2tf32(P[(wm + g8 + 8) * 68 + kc * 8 + q]);
            a[2] = f2tf32(P[(wm + g8) * 68 + kc * 8 + q + 4]);
            a[3] = f2tf32(P[(wm + g8 + 8) * 68 + kc * 8 + q + 4]);
#pragma unroll
            for (int u = 0; u < 8; u++) {
                uint32_t b[2];
                b[0] = __float_as_uint(Vst[(kc * 8 + q) * 72 + u * 8 + g8]);
                b[1] = __float_as_uint(Vst[(kc * 8 + q + 4) * 72 + u * 8 + g8]);
                mma_tf32(o[u], a, b);
            }
        }

        __syncthreads();   // RACE FIX: all warps done reading stage kt&1
                           // before anyone issues next cp.async into it
    }

    // ---- epilogue: normalize, write Y as bf16 planes for the out-proj ----
    const int b = bh >> 4, h = bh & 15;
    const float i0 = 1.0f / l0;
    const float i1 = 1.0f / l1;
#pragma unroll
    for (int u = 0; u < 8; u++) {
        const int c = u * 8 + 2 * q;
        const size_t e0 = ((size_t)b * S_LEN + row0) * EMB + h * 64 + c;
        const size_t e1 = ((size_t)b * S_LEN + row1) * EMB + h * 64 + c;
        const float y0 = o[u][0] * i0, y1 = o[u][1] * i0;
        const float y2 = o[u][2] * i1, y3 = o[u][3] * i1;
        uint16_t h0, lo0, h1, lo1, h2, lo2, h3, lo3;
        bf_split(y0, h0, lo0); bf_split(y1, h1, lo1);
        bf_split(y2, h2, lo2); bf_split(y3, h3, lo3);
        *(uint32_t*)&g_Yh[e0] = (uint32_t)h0 | ((uint32_t)h1 << 16);
        *(uint32_t*)&g_Yl[e0] = (uint32_t)lo0 | ((uint32_t)lo1 << 16);
        *(uint32_t*)&g_Yh[e1] = (uint32_t)h2 | ((uint32_t)h3 << 16);
        *(uint32_t*)&g_Yl[e1] = (uint32_t)lo2 | ((uint32_t)lo3 << 16);
    }
}

// ---------------------------------------------------------------------------
extern "C" void kernel_launch(void* const* d_in, const int* in_sizes, int n_in,
                              void* d_out, int out_size)
{
    (void)in_sizes; (void)n_in; (void)out_size;
    const float* x  = (const float*)d_in[0];
    const float* Wq = (const float*)d_in[1];
    const float* Wk = (const float*)d_in[2];
    const float* Wv = (const float*)d_in[3];
    const float* Wo = (const float*)d_in[4];
    float* out = (float*)d_out;

    static bool attr_done = false;       // idempotent setup (not a work guard)
    static uint16_t *pXh, *pXl, *pWh, *pWl;
    if (!attr_done) {
        cudaFuncSetAttribute(gemm_bf<true>,
                             cudaFuncAttributeMaxDynamicSharedMemorySize, GSMEM2);
        cudaFuncSetAttribute(gemm_bf<false>,
                             cudaFuncAttributeMaxDynamicSharedMemorySize, GSMEM2);
        cudaFuncSetAttribute(flash_mma,
                             cudaFuncAttributeMaxDynamicSharedMemorySize, FLASH_SMEM);
        cudaGetSymbolAddress((void**)&pXh, g_Xh);
        cudaGetSymbolAddress((void**)&pXl, g_Xl);
        cudaGetSymbolAddress((void**)&pWh, g_Wh);
        cudaGetSymbolAddress((void**)&pWl, g_Wl);
        attr_done = true;
    }

    // 0) split X and weights into bf16 hi/lo planes
    split_bf<<<8192, 256>>>((const float4*)x,  pXh, pXl, 2097152);
    split_bf<<<1024, 256>>>((const float4*)Wq, pWh,           pWl,           262144);
    split_bf<<<1024, 256>>>((const float4*)Wk, pWh + 1048576, pWl + 1048576, 262144);
    split_bf<<<1024, 256>>>((const float4*)Wv, pWh + 2097152, pWl + 2097152, 262144);
    split_bf<<<1024, 256>>>((const float4*)Wo, pWh + 3145728, pWl + 3145728, 262144);
    // 1) QKV projections (3xbf16; Q/K written as bf16 planes, V tf32)
    gemm_bf<true><<<dim3(64, 8, 3), 256, GSMEM2>>>(nullptr);
    // 2) Causal flash attention (3xbf16 QK, 1xTF32 PV, race-fixed, LPT)
    flash_mma<<<dim3(64, 16), 256, FLASH_SMEM>>>();
    // 3) Output projection (3xbf16)
    gemm_bf<false><<<dim3(64, 8), 256, GSMEM2>>>(out);
}